// round 2
// baseline (speedup 1.0000x reference)
#include <cuda_runtime.h>

#define SVOL  4096000        // 160^3
#define NTOT  8192000        // 2 * 160^3
#define NQ    2048000        // NTOT / 4
#define DHW   160

// dynamic shared memory layout (floats)
#define OFF_STAGE 0          // 36 rows * 48 pitch
#define OFF_ROWMN 1728       // 36 * 40
#define OFF_M2D   3168       // 3 * 34 * 40
#define OFF_ERO   7248       // 3 * 34 * 40
#define OFF_RMAX  11328      // 34 * 32
#define OFF_E2D   12416      // 3 * 32 * 32
#define OFF_XC    15488      // 3 * 32 * 32
#define SM_FLOATS 18560
#define SM_BYTES  (SM_FLOATS * 4)

#define PINF __int_as_float(0x7f800000)
#define NINF __int_as_float(0xff800000)

// accumulators: [0]=ce  [1..3]=intersect  [4..6]=pred_sum  [7..9]=targ_count
//               [10]=sum p_skel  [11]=sum p_skel*y  [12]=sum y_skel  [13]=sum y_skel*p
__device__ double g_acc[14];
__device__ float g_Xp[NTOT];
__device__ float g_Xp2[NTOT];
__device__ float g_Xy[NTOT];
__device__ float g_Xy2[NTOT];
__device__ float g_Porig[NTOT];
__device__ unsigned char g_Yu8[NTOT];

__device__ __forceinline__ float4 min3v(float4 a, float4 b, float4 c) {
    float4 o;
    o.x = fminf(a.x, fminf(b.x, c.x));
    o.y = fminf(a.y, fminf(b.y, c.y));
    o.z = fminf(a.z, fminf(b.z, c.z));
    o.w = fminf(a.w, fminf(b.w, c.w));
    return o;
}
__device__ __forceinline__ float4 max3v(float4 a, float4 b, float4 c) {
    float4 o;
    o.x = fmaxf(a.x, fmaxf(b.x, c.x));
    o.y = fmaxf(a.y, fmaxf(b.y, c.y));
    o.z = fmaxf(a.z, fmaxf(b.z, c.z));
    o.w = fmaxf(a.w, fmaxf(b.w, c.w));
    return o;
}

template <int NV>
__device__ __forceinline__ void blockAddTo(const float* vals, double* gout) {
    __shared__ float red[NV][8];
    int tid = threadIdx.x, lane = tid & 31, w = tid >> 5;
#pragma unroll
    for (int k = 0; k < NV; k++) {
        float v = vals[k];
#pragma unroll
        for (int o = 16; o; o >>= 1) v += __shfl_down_sync(0xffffffffu, v, o);
        if (lane == 0) red[k][w] = v;
    }
    __syncthreads();
    if (w == 0) {
#pragma unroll
        for (int k = 0; k < NV; k++) {
            float v = (lane < 8) ? red[k][lane] : 0.0f;
#pragma unroll
            for (int o = 4; o; o >>= 1) v += __shfl_down_sync(0xffffffffu, v, o);
            if (lane == 0) atomicAdd(&gout[k], (double)v);
        }
    }
}

__global__ void k_zero() {
    if (threadIdx.x < 14) g_acc[threadIdx.x] = 0.0;
}

// Fused: log-softmax, CE, dice accumulators, p_v / y_v buffer init.
// target is int32 (JAX x64 disabled -> requested int64 silently becomes int32).
__global__ void __launch_bounds__(256) k_init(const float* __restrict__ logits,
                                              const int* __restrict__ target) {
    int tid = threadIdx.x;
    int q = blockIdx.x * 256 + tid;            // quad index, exactly NQ threads
    int e = q * 4;
    int b = (e >= SVOL) ? 1 : 0;
    int s = e - b * SVOL;
    const float* lp = logits + (size_t)b * 3 * SVOL + s;
    float4 L0 = *(const float4*)(lp);
    float4 L1 = *(const float4*)(lp + SVOL);
    float4 L2 = *(const float4*)(lp + 2 * SVOL);
    int4 ti = ((const int4*)target)[q];
    int tg[4] = {ti.x, ti.y, ti.z, ti.w};
    float a0[4] = {L0.x, L0.y, L0.z, L0.w};
    float a1[4] = {L1.x, L1.y, L1.z, L1.w};
    float a2[4] = {L2.x, L2.y, L2.z, L2.w};

    float ce = 0.f, i0 = 0.f, i1 = 0.f, i2 = 0.f;
    float s0 = 0.f, s1 = 0.f, s2 = 0.f, c0 = 0.f, c1 = 0.f, c2 = 0.f;
    float pv[4], yv[4];
#pragma unroll
    for (int j = 0; j < 4; j++) {
        float x0 = a0[j], x1 = a1[j], x2 = a2[j];
        float m = fmaxf(x0, fmaxf(x1, x2));
        float e0 = __expf(x0 - m), e1 = __expf(x1 - m), e2 = __expf(x2 - m);
        float sum = e0 + e1 + e2;
        float inv = 1.0f / sum;
        float p0 = e0 * inv, p1 = e1 * inv, p2 = e2 * inv;
        float ls = __logf(sum);
        int t = tg[j];
        float lt = (t == 0) ? x0 : ((t == 1) ? x1 : x2);
        ce += (m + ls - lt);
        s0 += p0; s1 += p1; s2 += p2;
        if (t == 0)      { i0 += p0; c0 += 1.f; }
        else if (t == 1) { i1 += p1; c1 += 1.f; }
        else             { i2 += p2; c2 += 1.f; }
        pv[j] = fminf(fmaxf(1.0f - p0, 0.0f), 1.0f);
        yv[j] = (t != 0) ? 1.0f : 0.0f;
    }
    float4 PV = {pv[0], pv[1], pv[2], pv[3]};
    float4 YV = {yv[0], yv[1], yv[2], yv[3]};
    ((float4*)g_Xp)[q] = PV;
    ((float4*)g_Porig)[q] = PV;
    ((float4*)g_Xy)[q] = YV;
    uchar4 yu;
    yu.x = (unsigned char)(tg[0] != 0); yu.y = (unsigned char)(tg[1] != 0);
    yu.z = (unsigned char)(tg[2] != 0); yu.w = (unsigned char)(tg[3] != 0);
    ((uchar4*)g_Yu8)[q] = yu;

    float vals[10] = {ce, i0, i1, i2, s0, s1, s2, c0, c1, c2};
    blockAddTo<10>(vals, g_acc);
}

// One skeletonization iteration, fully fused:
//   eroded = minpool3^3(x)  (OOB = +inf, i.e. ignored)
//   opened = maxpool3^3(eroded) (OOB = -inf, i.e. ignored)
//   x_out  = relu(x - relu(opened - eroded))
// z-sliding-window, separable pools, float4 smem passes.
// Grid: 500 blocks = tensor(2) x batch(2) x zchunk(5) x tile(25). Tile 32x32, zchunk 32.
__global__ void __launch_bounds__(256) k_skel(int flip) {
    extern __shared__ float sm[];
    float* stage = sm + OFF_STAGE;   // [36][48], w_local = w + 8, pads = +inf
    float* rowmn = sm + OFF_ROWMN;   // [36][40], col m <-> w = m - 4
    float* m2d   = sm + OFF_M2D;     // ring3 [34][40], row r <-> h = r - 1
    float* ero   = sm + OFF_ERO;     // ring3 [34][40]
    float* rmax  = sm + OFF_RMAX;    // [34][32]
    float* e2d   = sm + OFF_E2D;     // ring3 [32][32]
    float* xcp   = sm + OFF_XC;      // ring3 [32][32]

    const float* srcP = flip ? g_Xp2 : g_Xp;
    float*       dstP = flip ? g_Xp  : g_Xp2;
    const float* srcY = flip ? g_Xy2 : g_Xy;
    float*       dstY = flip ? g_Xy  : g_Xy2;

    int tid = threadIdx.x;
    int bi = blockIdx.x;
    int tensor = bi / 250; int r = bi % 250;
    int b = r / 125; r %= 125;
    int zc = r / 25; int t = r % 25;
    int h0 = (t / 5) * 32, w0 = (t % 5) * 32;
    int z0 = zc * 32, z1 = z0 + 31;
    const float* src = tensor ? srcY : srcP;
    float* dst = tensor ? dstY : dstP;
    int base = b * SVOL;

    // one-time pad fill (cols 0..5 and 42..47 stay +inf forever)
    for (int i = tid; i < 432; i += 256) {
        int row = i / 12, c = i % 12;
        stage[row * 48 + ((c < 6) ? c : c + 36)] = PINF;
    }

    for (int zl = z0 - 2; zl <= z1 + 2; ++zl) {
        bool zok = ((unsigned)zl < 160u);
        // ---- A: stage x slice zl (w in [-2..33], h in [-2..33]) ----
        for (int i = tid; i < 288; i += 256) {           // vector part w 0..31
            int row = i >> 3, qw = i & 7;
            int h = h0 + row - 2;
            float4 v = {PINF, PINF, PINF, PINF};
            if (zok && (unsigned)h < 160u)
                v = *(const float4*)(src + base + (zl * 160 + h) * 160 + w0 + qw * 4);
            *(float4*)&stage[row * 48 + 8 + qw * 4] = v;
        }
        for (int i = tid; i < 144; i += 256) {           // halo scalars w in {-2,-1,32,33}
            int row = i >> 2, k = i & 3;
            int w = (k < 2) ? (k - 2) : (k + 30);
            int h = h0 + row - 2, ww = w0 + w;
            float v = PINF;
            if (zok && (unsigned)h < 160u && (unsigned)ww < 160u)
                v = src[base + (zl * 160 + h) * 160 + ww];
            stage[row * 48 + 8 + w] = v;
        }
        __syncthreads();
        // ---- B: row-min along w ----
        for (int i = tid; i < 360; i += 256) {
            int g = i % 10, row = i / 10;
            const float* sp = &stage[row * 48 + 4 + g * 4];
            float l = sp[-1]; float4 a = *(const float4*)sp; float rr = sp[4];
            float4 o;
            o.x = fminf(l,   fminf(a.x, a.y));
            o.y = fminf(a.x, fminf(a.y, a.z));
            o.z = fminf(a.y, fminf(a.z, a.w));
            o.w = fminf(a.z, fminf(a.w, rr));
            *(float4*)&rowmn[row * 40 + g * 4] = o;
        }
        __syncthreads();
        // ---- C: col-min -> m2d[zl]; z-min -> eroded[zl-1] ----
        int sl2 = (zl + 6) % 3;          // slot(zl)
        int sl1 = (zl + 5) % 3;          // slot(zl-1)
        int sl0 = (zl + 4) % 3;          // slot(zl-2)
        int ze = zl - 1;
        bool zev = ((unsigned)ze < 160u);
        for (int i = tid; i < 340; i += 256) {
            int g = i % 10, mrow = i / 10;
            int off = mrow * 40 + g * 4;
            float4 r0 = *(float4*)&rowmn[off];
            float4 r1 = *(float4*)&rowmn[off + 40];
            float4 r2 = *(float4*)&rowmn[off + 80];
            float4 v = min3v(r0, r1, r2);
            *(float4*)&m2d[sl2 * 1360 + off] = v;
            float4 e;
            if (zev) {
                float4 ma = *(float4*)&m2d[sl0 * 1360 + off];
                float4 mb = *(float4*)&m2d[sl1 * 1360 + off];
                e = min3v(v, ma, mb);
            } else {
                e.x = NINF; e.y = NINF; e.z = NINF; e.w = NINF;
            }
            *(float4*)&ero[sl1 * 1360 + off] = e;
        }
        __syncthreads();
        // ---- D: row-max of eroded[zl-1] ----
        for (int i = tid; i < 272; i += 256) {
            int g = i & 7, row = i >> 3;
            const float* ep = &ero[sl1 * 1360 + row * 40 + 4 + g * 4];
            float l = ep[-1]; float4 a = *(const float4*)ep; float rr = ep[4];
            float4 o;
            o.x = fmaxf(l,   fmaxf(a.x, a.y));
            o.y = fmaxf(a.x, fmaxf(a.y, a.z));
            o.z = fmaxf(a.y, fmaxf(a.z, a.w));
            o.w = fmaxf(a.z, fmaxf(a.w, rr));
            *(float4*)&rmax[row * 32 + g * 4] = o;
        }
        __syncthreads();
        // ---- E: col-max -> e2d[zl-1]; copy x center -> xc[zl] ----
        {
            int g = tid & 7, h = tid >> 3;    // exactly 256 items
            int off = h * 32 + g * 4;
            float4 r0 = *(float4*)&rmax[off];
            float4 r1 = *(float4*)&rmax[off + 32];
            float4 r2 = *(float4*)&rmax[off + 64];
            *(float4*)&e2d[sl1 * 1024 + off] = max3v(r0, r1, r2);
            *(float4*)&xcp[sl2 * 1024 + off] = *(float4*)&stage[(h + 2) * 48 + 8 + g * 4];
        }
        __syncthreads();
        // ---- F: output slice z = zl - 2 ----
        int z = zl - 2;
        if (z >= z0) {
            int g = tid & 7, h = tid >> 3;
            int off = h * 32 + g * 4;
            int ia = (z + 5) % 3, ib = (z + 6) % 3, ic = (z + 7) % 3;
            float4 ea = *(float4*)&e2d[ia * 1024 + off];
            float4 eb = *(float4*)&e2d[ib * 1024 + off];
            float4 ec_ = *(float4*)&e2d[ic * 1024 + off];
            float4 op = max3v(ea, eb, ec_);
            float4 er = *(float4*)&ero[ib * 1360 + (h + 1) * 40 + 4 + g * 4];
            float4 xv = *(float4*)&xcp[ib * 1024 + off];
            float4 o;
            o.x = fmaxf(xv.x - fmaxf(op.x - er.x, 0.f), 0.f);
            o.y = fmaxf(xv.y - fmaxf(op.y - er.y, 0.f), 0.f);
            o.z = fmaxf(xv.z - fmaxf(op.z - er.z, 0.f), 0.f);
            o.w = fmaxf(xv.w - fmaxf(op.w - er.w, 0.f), 0.f);
            *(float4*)(dst + base + (z * 160 + h0 + h) * 160 + w0 + g * 4) = o;
        }
        __syncthreads();
    }
}

// Final clDice sums: sum(p_skel), sum(p_skel*y), sum(y_skel), sum(y_skel*p_orig)
__global__ void __launch_bounds__(256) k_cl_reduce() {
    int q = blockIdx.x * 256 + threadIdx.x;
    float4 ps = ((const float4*)g_Xp)[q];       // p skeleton (8 iters -> back in g_Xp)
    float4 ys = ((const float4*)g_Xy)[q];       // y skeleton
    float4 po = ((const float4*)g_Porig)[q];
    uchar4 yu = ((const uchar4*)g_Yu8)[q];
    float y0 = yu.x ? 1.f : 0.f, y1 = yu.y ? 1.f : 0.f;
    float y2 = yu.z ? 1.f : 0.f, y3 = yu.w ? 1.f : 0.f;
    float sp  = ps.x + ps.y + ps.z + ps.w;
    float spy = ps.x * y0 + ps.y * y1 + ps.z * y2 + ps.w * y3;
    float sy  = ys.x + ys.y + ys.z + ys.w;
    float syp = ys.x * po.x + ys.y * po.y + ys.z * po.z + ys.w * po.w;
    float vals[4] = {sp, spy, sy, syp};
    blockAddTo<4>(vals, g_acc + 10);
}

__global__ void k_fin(float* out) {
    double ce = g_acc[0] / (double)NTOT;
    double dsum = 0.0;
#pragma unroll
    for (int c = 0; c < 3; c++) {
        double I = g_acc[1 + c], P = g_acc[4 + c], T = g_acc[7 + c];
        dsum += (2.0 * I + 1e-5) / (P + T + 1e-5);
    }
    double base = ce + (1.0 - dsum / 3.0);
    double tprec = g_acc[11] / (g_acc[10] + 1e-6);
    double tsens = g_acc[13] / (g_acc[12] + 1e-6);
    double cl = 2.0 * tprec * tsens / (tprec + tsens + 1e-6);
    out[0] = (float)(base + 0.5 * (1.0 - cl));
}

extern "C" void kernel_launch(void* const* d_in, const int* in_sizes, int n_in,
                              void* d_out, int out_size) {
    const float* logits = (const float*)d_in[0];
    const int* target = (const int*)d_in[1];

    cudaFuncSetAttribute((const void*)k_skel,
                         cudaFuncAttributeMaxDynamicSharedMemorySize, SM_BYTES);

    k_zero<<<1, 32>>>();
    k_init<<<NQ / 256, 256>>>(logits, target);
    for (int it = 0; it < 8; ++it)
        k_skel<<<500, 256, SM_BYTES>>>(it & 1);
    k_cl_reduce<<<NQ / 256, 256>>>();
    k_fin<<<1, 1>>>((float*)d_out);
}

// round 3
// speedup vs baseline: 2.0262x; 2.0262x over previous
#include <cuda_runtime.h>

#define SVOL  4096000        // 160^3
#define NTOT  8192000        // 2 * 160^3
#define NQ    2048000        // NTOT / 4

// ---- float skeleton smem layout (floats) ----
#define OFF_STAGE 0          // 36 rows * 48 pitch
#define OFF_ROWMN 1728       // 36 * 40
#define OFF_M2D   3168       // ring3 [34][40]
#define OFF_ERO   7248       // ring2 [34][40]
#define OFF_RMAX  9968       // 34 * 32
#define OFF_E2D   11056      // ring3 [32][32]
#define SM_FLOATS 14128
#define SM_BYTES  (SM_FLOATS * 4)

// ---- bit skeleton ----
#define W5    5              // words per row (160 bits)
#define WSL   800            // words per slice
#define WBAT  128000         // words per batch
#define YW    256000         // total words (2 batches)
#define YSM_WORDS 14400      // X[5][800] + A[5][800] + B[5][800] + C[3][800]
#define YSM_BYTES (YSM_WORDS * 4)

#define PINF __int_as_float(0x7f800000)
#define NINF __int_as_float(0xff800000)

// accumulators: [0]=ce [1..3]=intersect [4..6]=pred_sum [7..9]=targ_count
//               [10]=sum p_skel [11]=sum p_skel*y [12]=sum y_skel [13]=sum y_skel*p
__device__ double g_acc[14];
__device__ float g_Xp[NTOT];
__device__ float g_Xp2[NTOT];
__device__ float g_Porig[NTOT];
__device__ unsigned int g_Yb0[YW];   // original y (packed), never modified
__device__ unsigned int g_Yb[YW];    // working skeleton buffer
__device__ unsigned int g_Yb2[YW];

__device__ __forceinline__ float4 min3v(float4 a, float4 b, float4 c) {
    float4 o;
    o.x = fminf(a.x, fminf(b.x, c.x));
    o.y = fminf(a.y, fminf(b.y, c.y));
    o.z = fminf(a.z, fminf(b.z, c.z));
    o.w = fminf(a.w, fminf(b.w, c.w));
    return o;
}
__device__ __forceinline__ float4 max3v(float4 a, float4 b, float4 c) {
    float4 o;
    o.x = fmaxf(a.x, fmaxf(b.x, c.x));
    o.y = fmaxf(a.y, fmaxf(b.y, c.y));
    o.z = fmaxf(a.z, fmaxf(b.z, c.z));
    o.w = fmaxf(a.w, fmaxf(b.w, c.w));
    return o;
}

template <int NV>
__device__ __forceinline__ void blockAddTo(const float* vals, double* gout) {
    __shared__ float red[NV][8];
    int tid = threadIdx.x, lane = tid & 31, w = tid >> 5;
#pragma unroll
    for (int k = 0; k < NV; k++) {
        float v = vals[k];
#pragma unroll
        for (int o = 16; o; o >>= 1) v += __shfl_down_sync(0xffffffffu, v, o);
        if (lane == 0) red[k][w] = v;
    }
    __syncthreads();
    if (w == 0) {
#pragma unroll
        for (int k = 0; k < NV; k++) {
            float v = (lane < 8) ? red[k][lane] : 0.0f;
#pragma unroll
            for (int o = 4; o; o >>= 1) v += __shfl_down_sync(0xffffffffu, v, o);
            if (lane == 0) atomicAdd(&gout[k], (double)v);
        }
    }
}

__global__ void k_zero() {
    if (threadIdx.x < 14) g_acc[threadIdx.x] = 0.0;
}

// Fused: log-softmax, CE, dice accumulators, p_v init, y bit-packing.
__global__ void __launch_bounds__(256) k_init(const float* __restrict__ logits,
                                              const int* __restrict__ target) {
    __shared__ unsigned char nib[256];
    int tid = threadIdx.x;
    int q = blockIdx.x * 256 + tid;            // quad index, exactly NQ threads
    int e = q * 4;
    int b = (e >= SVOL) ? 1 : 0;
    int s = e - b * SVOL;
    const float* lp = logits + (size_t)b * 3 * SVOL + s;
    float4 L0 = *(const float4*)(lp);
    float4 L1 = *(const float4*)(lp + SVOL);
    float4 L2 = *(const float4*)(lp + 2 * SVOL);
    int4 ti = ((const int4*)target)[q];
    int tg[4] = {ti.x, ti.y, ti.z, ti.w};
    float a0[4] = {L0.x, L0.y, L0.z, L0.w};
    float a1[4] = {L1.x, L1.y, L1.z, L1.w};
    float a2[4] = {L2.x, L2.y, L2.z, L2.w};

    float ce = 0.f, i0 = 0.f, i1 = 0.f, i2 = 0.f;
    float s0 = 0.f, s1 = 0.f, s2 = 0.f, c0 = 0.f, c1 = 0.f, c2 = 0.f;
    float pv[4];
    unsigned nb = 0;
#pragma unroll
    for (int j = 0; j < 4; j++) {
        float x0 = a0[j], x1 = a1[j], x2 = a2[j];
        float m = fmaxf(x0, fmaxf(x1, x2));
        float e0 = __expf(x0 - m), e1 = __expf(x1 - m), e2 = __expf(x2 - m);
        float sum = e0 + e1 + e2;
        float inv = 1.0f / sum;
        float p0 = e0 * inv, p1 = e1 * inv, p2 = e2 * inv;
        float ls = __logf(sum);
        int t = tg[j];
        float lt = (t == 0) ? x0 : ((t == 1) ? x1 : x2);
        ce += (m + ls - lt);
        s0 += p0; s1 += p1; s2 += p2;
        if (t == 0)      { i0 += p0; c0 += 1.f; }
        else if (t == 1) { i1 += p1; c1 += 1.f; }
        else             { i2 += p2; c2 += 1.f; }
        pv[j] = fminf(fmaxf(1.0f - p0, 0.0f), 1.0f);
        if (t != 0) nb |= (1u << j);
    }
    float4 PV = {pv[0], pv[1], pv[2], pv[3]};
    ((float4*)g_Xp)[q] = PV;
    ((float4*)g_Porig)[q] = PV;
    nib[tid] = (unsigned char)nb;
    __syncthreads();
    if (tid < 32) {
        unsigned w = 0;
#pragma unroll
        for (int k = 0; k < 8; k++) w |= ((unsigned)nib[tid * 8 + k]) << (4 * k);
        int wi = blockIdx.x * 32 + tid;
        g_Yb0[wi] = w;
        g_Yb[wi] = w;
    }

    float vals[10] = {ce, i0, i1, i2, s0, s1, s2, c0, c1, c2};
    blockAddTo<10>(vals, g_acc);
}

// One float skeletonization iteration (p tensor only):
//   eroded = minpool3^3(x)  (OOB ignored)
//   opened = maxpool3^3(eroded) (OOB ignored)
//   x_out  = relu(x - relu(opened - eroded))
// Grid: 500 blocks = batch(2) x zchunk(10,16 slices) x tile(25 of 32x32).
__global__ void __launch_bounds__(256) k_skel(int flip) {
    extern __shared__ float sm[];
    float* stage = sm + OFF_STAGE;   // [36][48], w_local = w + 8, pads = +inf
    float* rowmn = sm + OFF_ROWMN;   // [36][40]
    float* m2d   = sm + OFF_M2D;     // ring3 [34][40]
    float* ero   = sm + OFF_ERO;     // ring2 [34][40]
    float* rmax  = sm + OFF_RMAX;    // [34][32]
    float* e2d   = sm + OFF_E2D;     // ring3 [32][32]

    const float* src = flip ? g_Xp2 : g_Xp;
    float*       dst = flip ? g_Xp  : g_Xp2;

    int tid = threadIdx.x;
    int r = blockIdx.x;
    int b = r / 250; r %= 250;
    int zc = r / 25; int t = r % 25;
    int h0 = (t / 5) * 32, w0 = (t % 5) * 32;
    int z0 = zc * 16, z1 = z0 + 15;
    int base = b * SVOL;

    // one-time pad fill (cols 0..5 and 42..47 stay +inf forever)
    for (int i = tid; i < 432; i += 256) {
        int row = i / 12, c = i % 12;
        stage[row * 48 + ((c < 6) ? c : c + 36)] = PINF;
    }

    for (int zl = z0 - 2; zl <= z1 + 2; ++zl) {
        bool zok = ((unsigned)zl < 160u);
        // ---- A: stage x slice zl (w in [-2..33], h in [-2..33]) ----
        for (int i = tid; i < 288; i += 256) {           // vector part w 0..31
            int row = i >> 3, qw = i & 7;
            int h = h0 + row - 2;
            float4 v = {PINF, PINF, PINF, PINF};
            if (zok && (unsigned)h < 160u)
                v = *(const float4*)(src + base + (zl * 160 + h) * 160 + w0 + qw * 4);
            *(float4*)&stage[row * 48 + 8 + qw * 4] = v;
        }
        for (int i = tid; i < 144; i += 256) {           // halo scalars w in {-2,-1,32,33}
            int row = i >> 2, k = i & 3;
            int w = (k < 2) ? (k - 2) : (k + 30);
            int h = h0 + row - 2, ww = w0 + w;
            float v = PINF;
            if (zok && (unsigned)h < 160u && (unsigned)ww < 160u)
                v = src[base + (zl * 160 + h) * 160 + ww];
            stage[row * 48 + 8 + w] = v;
        }
        __syncthreads();
        // ---- B: row-min along w ----
        for (int i = tid; i < 360; i += 256) {
            int g = i % 10, row = i / 10;
            const float* sp = &stage[row * 48 + 4 + g * 4];
            float l = sp[-1]; float4 a = *(const float4*)sp; float rr = sp[4];
            float4 o;
            o.x = fminf(l,   fminf(a.x, a.y));
            o.y = fminf(a.x, fminf(a.y, a.z));
            o.z = fminf(a.y, fminf(a.z, a.w));
            o.w = fminf(a.z, fminf(a.w, rr));
            *(float4*)&rowmn[row * 40 + g * 4] = o;
        }
        __syncthreads();
        // ---- C: col-min -> m2d[zl] (ring3); z-min -> ero[zl-1] (ring2) ----
        int sl2 = (zl + 6) % 3;          // slot(zl)
        int sl1 = (zl + 5) % 3;          // slot(zl-1)
        int sl0 = (zl + 4) % 3;          // slot(zl-2)
        int ze = zl - 1;
        int eW = (ze + 2) & 1;           // ero write slot
        bool zev = ((unsigned)ze < 160u);
        for (int i = tid; i < 340; i += 256) {
            int g = i % 10, mrow = i / 10;
            int off = mrow * 40 + g * 4;
            float4 r0 = *(float4*)&rowmn[off];
            float4 r1 = *(float4*)&rowmn[off + 40];
            float4 r2 = *(float4*)&rowmn[off + 80];
            float4 v = min3v(r0, r1, r2);
            *(float4*)&m2d[sl2 * 1360 + off] = v;
            float4 e;
            if (zev) {
                float4 ma = *(float4*)&m2d[sl0 * 1360 + off];
                float4 mb = *(float4*)&m2d[sl1 * 1360 + off];
                e = min3v(v, ma, mb);
            } else {
                e.x = NINF; e.y = NINF; e.z = NINF; e.w = NINF;
            }
            *(float4*)&ero[eW * 1360 + off] = e;
        }
        __syncthreads();
        // ---- D: row-max of ero[zl-1] ----
        for (int i = tid; i < 272; i += 256) {
            int g = i & 7, row = i >> 3;
            const float* ep = &ero[eW * 1360 + row * 40 + 4 + g * 4];
            float l = ep[-1]; float4 a = *(const float4*)ep; float rr = ep[4];
            float4 o;
            o.x = fmaxf(l,   fmaxf(a.x, a.y));
            o.y = fmaxf(a.x, fmaxf(a.y, a.z));
            o.z = fmaxf(a.y, fmaxf(a.z, a.w));
            o.w = fmaxf(a.z, fmaxf(a.w, rr));
            *(float4*)&rmax[row * 32 + g * 4] = o;
        }
        __syncthreads();
        // ---- E: col-max -> e2d[zl-1] (ring3) ----
        {
            int g = tid & 7, h = tid >> 3;    // exactly 256 items
            int off = h * 32 + g * 4;
            float4 r0 = *(float4*)&rmax[off];
            float4 r1 = *(float4*)&rmax[off + 32];
            float4 r2 = *(float4*)&rmax[off + 64];
            *(float4*)&e2d[sl1 * 1024 + off] = max3v(r0, r1, r2);
        }
        __syncthreads();
        // ---- F: output slice z = zl - 2 ----
        int z = zl - 2;
        if (z >= z0) {
            int g = tid & 7, h = tid >> 3;
            int off = h * 32 + g * 4;
            int ia = (z + 5) % 3, ib = (z + 6) % 3, ic = (z + 7) % 3;
            float4 ea = *(float4*)&e2d[ia * 1024 + off];
            float4 eb = *(float4*)&e2d[ib * 1024 + off];
            float4 ec_ = *(float4*)&e2d[ic * 1024 + off];
            float4 op = max3v(ea, eb, ec_);
            float4 er = *(float4*)&ero[(z & 1) * 1360 + (h + 1) * 40 + 4 + g * 4];
            float4 xv = *(const float4*)(src + base + (z * 160 + h0 + h) * 160 + w0 + g * 4);
            float4 o;
            o.x = fmaxf(xv.x - fmaxf(op.x - er.x, 0.f), 0.f);
            o.y = fmaxf(xv.y - fmaxf(op.y - er.y, 0.f), 0.f);
            o.z = fmaxf(xv.z - fmaxf(op.z - er.z, 0.f), 0.f);
            o.w = fmaxf(xv.w - fmaxf(op.w - er.w, 0.f), 0.f);
            *(float4*)(dst + base + (z * 160 + h0 + h) * 160 + w0 + g * 4) = o;
        }
        __syncthreads();
    }
}

// One bit-domain skeletonization iteration for binary y.
// Block = (batch, z). smem words: X[5][800] | A[5][800] | B[5][800] | C[3][800]
__global__ void __launch_bounds__(256) k_yskel(int flip) {
    extern __shared__ unsigned int su[];
    unsigned int* X = su;            // x slices z-2..z+2 (OOB = all ones)
    unsigned int* A = su + 4000;     // scratch (wE, then wD)
    unsigned int* B = su + 8000;     // scratch (hwE, then hD)
    unsigned int* C = su + 12000;    // ero slices z-1..z+1

    const unsigned int* src = flip ? g_Yb2 : g_Yb;
    unsigned int*       dst = flip ? g_Yb  : g_Yb2;

    int tid = threadIdx.x;
    int b = blockIdx.x / 160;
    int z = blockIdx.x % 160;
    int gbase = b * WBAT;

    // load 5 slices
    for (int i = tid; i < 4000; i += 256) {
        int s = i / WSL, w = i - s * WSL;
        int zs = z - 2 + s;
        X[i] = ((unsigned)zs < 160u) ? src[gbase + zs * WSL + w] : 0xFFFFFFFFu;
    }
    __syncthreads();
    // w-erode (OOB fill = 1)
    for (int i = tid; i < 4000; i += 256) {
        int rw = i % WSL;            // word within slice
        int j = rw % W5;
        unsigned w = X[i];
        unsigned lft = j > 0 ? X[i - 1] : 0xFFFFFFFFu;
        unsigned rgt = j < 4 ? X[i + 1] : 0xFFFFFFFFu;
        A[i] = w & ((w << 1) | (lft >> 31)) & ((w >> 1) | (rgt << 31));
    }
    __syncthreads();
    // h-erode (OOB rows = 1)
    for (int i = tid; i < 4000; i += 256) {
        int s = i / WSL, rw = i - s * WSL;
        int r = rw / W5;
        unsigned w = A[i];
        unsigned up = r > 0   ? A[i - W5] : 0xFFFFFFFFu;
        unsigned dn = r < 159 ? A[i + W5] : 0xFFFFFFFFu;
        B[i] = w & up & dn;
    }
    __syncthreads();
    // z-erode -> ero slices z-1..z+1 (OOB slice -> 0: contributes nothing to open)
    for (int i = tid; i < 2400; i += 256) {
        int t = i / WSL, w = i - t * WSL;
        int zi = z - 1 + t;
        unsigned e = B[t * WSL + w] & B[(t + 1) * WSL + w] & B[(t + 2) * WSL + w];
        C[i] = ((unsigned)zi < 160u) ? e : 0u;
    }
    __syncthreads();
    // w-dilate (OOB fill = 0)
    for (int i = tid; i < 2400; i += 256) {
        int rw = i % WSL;
        int j = rw % W5;
        unsigned w = C[i];
        unsigned lft = j > 0 ? C[i - 1] : 0u;
        unsigned rgt = j < 4 ? C[i + 1] : 0u;
        A[i] = w | (w << 1) | (lft >> 31) | (w >> 1) | (rgt << 31);
    }
    __syncthreads();
    // h-dilate
    for (int i = tid; i < 2400; i += 256) {
        int t = i / WSL, rw = i - t * WSL;
        int r = rw / W5;
        unsigned w = A[i];
        unsigned up = r > 0   ? A[i - W5] : 0u;
        unsigned dn = r < 159 ? A[i + W5] : 0u;
        B[i] = w | up | dn;
    }
    __syncthreads();
    // z-dilate -> open(z); combine: y_new = y & (~open | ero)
    for (int i = tid; i < 800; i += 256) {
        unsigned open = B[i] | B[WSL + i] | B[2 * WSL + i];
        unsigned eroz = C[WSL + i];
        unsigned x = X[2 * WSL + i];
        dst[gbase + z * WSL + i] = x & (~open | eroz);
    }
}

// Final clDice sums: sum(p_skel), sum(p_skel*y), sum(y_skel), sum(y_skel*p_orig)
__global__ void __launch_bounds__(256) k_cl_reduce() {
    int q = blockIdx.x * 256 + threadIdx.x;
    float4 ps = ((const float4*)g_Xp)[q];       // p skeleton (8 iters -> back in g_Xp)
    float4 po = ((const float4*)g_Porig)[q];
    unsigned wS = g_Yb[q >> 3];                 // y skeleton bits (8 iters -> g_Yb)
    unsigned wO = g_Yb0[q >> 3];                // original y bits
    int sh = (q & 7) * 4;
    unsigned ns = (wS >> sh) & 0xFu;
    unsigned no = (wO >> sh) & 0xFu;
    float ys0 = (float)(ns & 1),        ys1 = (float)((ns >> 1) & 1);
    float ys2 = (float)((ns >> 2) & 1), ys3 = (float)((ns >> 3) & 1);
    float yo0 = (float)(no & 1),        yo1 = (float)((no >> 1) & 1);
    float yo2 = (float)((no >> 2) & 1), yo3 = (float)((no >> 3) & 1);
    float sp  = ps.x + ps.y + ps.z + ps.w;
    float spy = ps.x * yo0 + ps.y * yo1 + ps.z * yo2 + ps.w * yo3;
    float sy  = ys0 + ys1 + ys2 + ys3;
    float syp = ys0 * po.x + ys1 * po.y + ys2 * po.z + ys3 * po.w;
    float vals[4] = {sp, spy, sy, syp};
    blockAddTo<4>(vals, g_acc + 10);
}

__global__ void k_fin(float* out) {
    double ce = g_acc[0] / (double)NTOT;
    double dsum = 0.0;
#pragma unroll
    for (int c = 0; c < 3; c++) {
        double I = g_acc[1 + c], P = g_acc[4 + c], T = g_acc[7 + c];
        dsum += (2.0 * I + 1e-5) / (P + T + 1e-5);
    }
    double base = ce + (1.0 - dsum / 3.0);
    double tprec = g_acc[11] / (g_acc[10] + 1e-6);
    double tsens = g_acc[13] / (g_acc[12] + 1e-6);
    double cl = 2.0 * tprec * tsens / (tprec + tsens + 1e-6);
    out[0] = (float)(base + 0.5 * (1.0 - cl));
}

extern "C" void kernel_launch(void* const* d_in, const int* in_sizes, int n_in,
                              void* d_out, int out_size) {
    const float* logits = (const float*)d_in[0];
    const int* target = (const int*)d_in[1];

    cudaFuncSetAttribute((const void*)k_skel,
                         cudaFuncAttributeMaxDynamicSharedMemorySize, SM_BYTES);
    cudaFuncSetAttribute((const void*)k_yskel,
                         cudaFuncAttributeMaxDynamicSharedMemorySize, YSM_BYTES);

    k_zero<<<1, 32>>>();
    k_init<<<NQ / 256, 256>>>(logits, target);
    for (int it = 0; it < 8; ++it) {
        k_skel<<<500, 256, SM_BYTES>>>(it & 1);
        k_yskel<<<320, 256, YSM_BYTES>>>(it & 1);
    }
    k_cl_reduce<<<NQ / 256, 256>>>();
    k_fin<<<1, 1>>>((float*)d_out);
}

// round 4
// speedup vs baseline: 2.6372x; 1.3015x over previous
#include <cuda_runtime.h>

#define SVOL  4096000        // 160^3
#define NTOT  8192000        // 2 * 160^3
#define NQ    2048000        // NTOT / 4

// ---- float skeleton smem layout (floats) ----
#define OFF_STAGE 0          // 36 rows * 48 pitch
#define OFF_ROWMN 1728       // 36 * 40
#define OFF_M2D   3168       // ring3 [34][40]
#define OFF_ERO   7248       // ring2 [34][40]
#define OFF_RMAX  9968       // 34 * 32
#define OFF_E2D   11056      // ring3 [32][32]
#define SM_FLOATS 14128
#define SM_BYTES  (SM_FLOATS * 4)

// ---- bit skeleton (y) smem layout (words) ----
#define W5    5              // words per row (160 bits)
#define WSL   800            // words per slice
#define WBAT  128000         // words per batch
#define YW    256000
#define YOFF_X   0           // ring4 [800]
#define YOFF_WA  3200        // [800]
#define YOFF_WH  4000        // ring3 [800]
#define YOFF_E   6400        // ring2 [800]
#define YOFF_WD  8000        // [800]
#define YOFF_D   8800        // ring3 [800]

#define PINF __int_as_float(0x7f800000)
#define NINF __int_as_float(0xff800000)

// accumulators: [0]=ce [1..3]=intersect [4..6]=pred_sum [7..9]=targ_count
//               [10]=sum p_skel [11]=sum p_skel*y [12]=sum y_skel [13]=sum y_skel*p
__device__ double g_acc[14];
__device__ float g_Xp[NTOT];
__device__ float g_Xp2[NTOT];
__device__ float g_Porig[NTOT];
__device__ unsigned int g_Yb0[YW];   // original y (packed), never modified
__device__ unsigned int g_Yb[YW];    // working skeleton buffer
__device__ unsigned int g_Yb2[YW];

__device__ __forceinline__ float4 min3v(float4 a, float4 b, float4 c) {
    float4 o;
    o.x = fminf(a.x, fminf(b.x, c.x));
    o.y = fminf(a.y, fminf(b.y, c.y));
    o.z = fminf(a.z, fminf(b.z, c.z));
    o.w = fminf(a.w, fminf(b.w, c.w));
    return o;
}
__device__ __forceinline__ float4 max3v(float4 a, float4 b, float4 c) {
    float4 o;
    o.x = fmaxf(a.x, fmaxf(b.x, c.x));
    o.y = fmaxf(a.y, fmaxf(b.y, c.y));
    o.z = fmaxf(a.z, fmaxf(b.z, c.z));
    o.w = fmaxf(a.w, fmaxf(b.w, c.w));
    return o;
}

template <int NV>
__device__ __forceinline__ void blockAddTo(const float* vals, double* gout) {
    __shared__ float red[NV][8];
    int tid = threadIdx.x, lane = tid & 31, w = tid >> 5;
#pragma unroll
    for (int k = 0; k < NV; k++) {
        float v = vals[k];
#pragma unroll
        for (int o = 16; o; o >>= 1) v += __shfl_down_sync(0xffffffffu, v, o);
        if (lane == 0) red[k][w] = v;
    }
    __syncthreads();
    if (w == 0) {
#pragma unroll
        for (int k = 0; k < NV; k++) {
            float v = (lane < 8) ? red[k][lane] : 0.0f;
#pragma unroll
            for (int o = 4; o; o >>= 1) v += __shfl_down_sync(0xffffffffu, v, o);
            if (lane == 0) atomicAdd(&gout[k], (double)v);
        }
    }
}

__global__ void k_zero() {
    if (threadIdx.x < 14) g_acc[threadIdx.x] = 0.0;
}

// Fused: log-softmax, CE, dice accumulators, p_v init, y bit-packing.
__global__ void __launch_bounds__(256) k_init(const float* __restrict__ logits,
                                              const int* __restrict__ target) {
    __shared__ unsigned char nib[256];
    int tid = threadIdx.x;
    int q = blockIdx.x * 256 + tid;            // quad index, exactly NQ threads
    int e = q * 4;
    int b = (e >= SVOL) ? 1 : 0;
    int s = e - b * SVOL;
    const float* lp = logits + (size_t)b * 3 * SVOL + s;
    float4 L0 = *(const float4*)(lp);
    float4 L1 = *(const float4*)(lp + SVOL);
    float4 L2 = *(const float4*)(lp + 2 * SVOL);
    int4 ti = ((const int4*)target)[q];
    int tg[4] = {ti.x, ti.y, ti.z, ti.w};
    float a0[4] = {L0.x, L0.y, L0.z, L0.w};
    float a1[4] = {L1.x, L1.y, L1.z, L1.w};
    float a2[4] = {L2.x, L2.y, L2.z, L2.w};

    float ce = 0.f, i0 = 0.f, i1 = 0.f, i2 = 0.f;
    float s0 = 0.f, s1 = 0.f, s2 = 0.f, c0 = 0.f, c1 = 0.f, c2 = 0.f;
    float pv[4];
    unsigned nb = 0;
#pragma unroll
    for (int j = 0; j < 4; j++) {
        float x0 = a0[j], x1 = a1[j], x2 = a2[j];
        float m = fmaxf(x0, fmaxf(x1, x2));
        float e0 = __expf(x0 - m), e1 = __expf(x1 - m), e2 = __expf(x2 - m);
        float sum = e0 + e1 + e2;
        float inv = 1.0f / sum;
        float p0 = e0 * inv, p1 = e1 * inv, p2 = e2 * inv;
        float ls = __logf(sum);
        int t = tg[j];
        float lt = (t == 0) ? x0 : ((t == 1) ? x1 : x2);
        ce += (m + ls - lt);
        s0 += p0; s1 += p1; s2 += p2;
        if (t == 0)      { i0 += p0; c0 += 1.f; }
        else if (t == 1) { i1 += p1; c1 += 1.f; }
        else             { i2 += p2; c2 += 1.f; }
        pv[j] = fminf(fmaxf(1.0f - p0, 0.0f), 1.0f);
        if (t != 0) nb |= (1u << j);
    }
    float4 PV = {pv[0], pv[1], pv[2], pv[3]};
    ((float4*)g_Xp)[q] = PV;
    ((float4*)g_Porig)[q] = PV;
    nib[tid] = (unsigned char)nb;
    __syncthreads();
    if (tid < 32) {
        unsigned w = 0;
#pragma unroll
        for (int k = 0; k < 8; k++) w |= ((unsigned)nib[tid * 8 + k]) << (4 * k);
        int wi = blockIdx.x * 32 + tid;
        g_Yb0[wi] = w;
        g_Yb[wi] = w;
    }

    float vals[10] = {ce, i0, i1, i2, s0, s1, s2, c0, c1, c2};
    blockAddTo<10>(vals, g_acc);
}

// ---------------- merged skeleton iteration -----------------
// blocks [0,500): float p skeleton. blocks [500,540): bit y skeleton.

__device__ __forceinline__ void p_skel_block(float* sm, int bi, int flip) {
    float* stage = sm + OFF_STAGE;   // [36][48], w_local = w + 8, pads = +inf
    float* rowmn = sm + OFF_ROWMN;   // [36][40]
    float* m2d   = sm + OFF_M2D;     // ring3 [34][40]
    float* ero   = sm + OFF_ERO;     // ring2 [34][40]
    float* rmax  = sm + OFF_RMAX;    // [34][32]
    float* e2d   = sm + OFF_E2D;     // ring3 [32][32]

    const float* src = flip ? g_Xp2 : g_Xp;
    float*       dst = flip ? g_Xp  : g_Xp2;

    int tid = threadIdx.x;
    int r = bi;
    int b = r / 250; r %= 250;
    int zc = r / 25; int t = r % 25;
    int h0 = (t / 5) * 32, w0 = (t % 5) * 32;
    int z0 = zc * 16, z1 = z0 + 15;
    int base = b * SVOL;

    // one-time pad fill (cols 0..5 and 42..47 stay +inf forever)
    for (int i = tid; i < 432; i += 256) {
        int row = i / 12, c = i % 12;
        stage[row * 48 + ((c < 6) ? c : c + 36)] = PINF;
    }

    for (int zl = z0 - 2; zl <= z1 + 2; ++zl) {
        bool zok = ((unsigned)zl < 160u);
        // ---- A: stage x slice zl ----
        for (int i = tid; i < 288; i += 256) {           // vector part w 0..31
            int row = i >> 3, qw = i & 7;
            int h = h0 + row - 2;
            float4 v = {PINF, PINF, PINF, PINF};
            if (zok && (unsigned)h < 160u)
                v = *(const float4*)(src + base + (zl * 160 + h) * 160 + w0 + qw * 4);
            *(float4*)&stage[row * 48 + 8 + qw * 4] = v;
        }
        for (int i = tid; i < 144; i += 256) {           // halo scalars w in {-2,-1,32,33}
            int row = i >> 2, k = i & 3;
            int w = (k < 2) ? (k - 2) : (k + 30);
            int h = h0 + row - 2, ww = w0 + w;
            float v = PINF;
            if (zok && (unsigned)h < 160u && (unsigned)ww < 160u)
                v = src[base + (zl * 160 + h) * 160 + ww];
            stage[row * 48 + 8 + w] = v;
        }
        __syncthreads();
        // ---- B: row-min along w ----
        for (int i = tid; i < 360; i += 256) {
            int g = i % 10, row = i / 10;
            const float* sp = &stage[row * 48 + 4 + g * 4];
            float l = sp[-1]; float4 a = *(const float4*)sp; float rr = sp[4];
            float4 o;
            o.x = fminf(l,   fminf(a.x, a.y));
            o.y = fminf(a.x, fminf(a.y, a.z));
            o.z = fminf(a.y, fminf(a.z, a.w));
            o.w = fminf(a.z, fminf(a.w, rr));
            *(float4*)&rowmn[row * 40 + g * 4] = o;
        }
        __syncthreads();
        // ---- C: col-min -> m2d[zl] (ring3); z-min -> ero[zl-1] (ring2) ----
        int sl2 = (zl + 6) % 3;          // slot(zl)
        int sl1 = (zl + 5) % 3;          // slot(zl-1)
        int sl0 = (zl + 4) % 3;          // slot(zl-2)
        int ze = zl - 1;
        int eW = (ze + 2) & 1;           // ero write slot (parity of ze)
        bool zev = ((unsigned)ze < 160u);
        for (int i = tid; i < 340; i += 256) {
            int g = i % 10, mrow = i / 10;
            int off = mrow * 40 + g * 4;
            float4 r0 = *(float4*)&rowmn[off];
            float4 r1 = *(float4*)&rowmn[off + 40];
            float4 r2 = *(float4*)&rowmn[off + 80];
            float4 v = min3v(r0, r1, r2);
            *(float4*)&m2d[sl2 * 1360 + off] = v;
            float4 e;
            if (zev) {
                float4 ma = *(float4*)&m2d[sl0 * 1360 + off];
                float4 mb = *(float4*)&m2d[sl1 * 1360 + off];
                e = min3v(v, ma, mb);
            } else {
                e.x = NINF; e.y = NINF; e.z = NINF; e.w = NINF;
            }
            *(float4*)&ero[eW * 1360 + off] = e;
        }
        __syncthreads();
        // ---- D: row-max of ero[zl-1] ----
        for (int i = tid; i < 272; i += 256) {
            int g = i & 7, row = i >> 3;
            const float* ep = &ero[eW * 1360 + row * 40 + 4 + g * 4];
            float l = ep[-1]; float4 a = *(const float4*)ep; float rr = ep[4];
            float4 o;
            o.x = fmaxf(l,   fmaxf(a.x, a.y));
            o.y = fmaxf(a.x, fmaxf(a.y, a.z));
            o.z = fmaxf(a.y, fmaxf(a.z, a.w));
            o.w = fmaxf(a.z, fmaxf(a.w, rr));
            *(float4*)&rmax[row * 32 + g * 4] = o;
        }
        __syncthreads();
        // ---- E+F fused: col-max -> e2d[zl-1]; output slice z = zl-2 ----
        {
            int g = tid & 7, h = tid >> 3;    // exactly 256 items
            int off = h * 32 + g * 4;
            float4 r0 = *(float4*)&rmax[off];
            float4 r1 = *(float4*)&rmax[off + 32];
            float4 r2 = *(float4*)&rmax[off + 64];
            float4 v = max3v(r0, r1, r2);     // e2d for slice zl-1
            *(float4*)&e2d[sl1 * 1024 + off] = v;

            int z = zl - 2;
            if (z >= z0) {
                int ia = (z + 5) % 3, ib = (z + 6) % 3;   // ic == sl1 -> v in regs
                float4 ea = *(float4*)&e2d[ia * 1024 + off];
                float4 eb = *(float4*)&e2d[ib * 1024 + off];
                float4 op = max3v(ea, eb, v);
                float4 er = *(float4*)&ero[(z & 1) * 1360 + (h + 1) * 40 + 4 + g * 4];
                float4 xv = *(const float4*)(src + base + (z * 160 + h0 + h) * 160 + w0 + g * 4);
                float4 o;
                o.x = fmaxf(xv.x - fmaxf(op.x - er.x, 0.f), 0.f);
                o.y = fmaxf(xv.y - fmaxf(op.y - er.y, 0.f), 0.f);
                o.z = fmaxf(xv.z - fmaxf(op.z - er.z, 0.f), 0.f);
                o.w = fmaxf(xv.w - fmaxf(op.w - er.w, 0.f), 0.f);
                *(float4*)(dst + base + (z * 160 + h0 + h) * 160 + w0 + g * 4) = o;
            }
        }
        // no trailing sync: every cross-step hazard has >=1 barrier in between
    }
}

// Bit-domain y skeleton, chunked z-ring: 8 output slices per block.
__device__ __forceinline__ void y_skel_block(unsigned int* su, int bi2, int flip) {
    unsigned int* X  = su + YOFF_X;    // ring4
    unsigned int* WA = su + YOFF_WA;
    unsigned int* WH = su + YOFF_WH;   // ring3
    unsigned int* E  = su + YOFF_E;    // ring2
    unsigned int* WD = su + YOFF_WD;
    unsigned int* D  = su + YOFF_D;    // ring3

    const unsigned int* src = flip ? g_Yb2 : g_Yb;
    unsigned int*       dst = flip ? g_Yb  : g_Yb2;

    int tid = threadIdx.x;
    int b = bi2 / 20, c = bi2 % 20;
    int z0 = c * 8, z1 = z0 + 7;
    int gbase = b * WBAT;

    for (int zl = z0 - 2; zl <= z1 + 2; ++zl) {
        int xs = (zl + 4) & 3;
        // P1: load X slice zl (OOB = all ones)
        {
            bool zok = ((unsigned)zl < 160u);
            for (int i = tid; i < 800; i += 256)
                X[xs * 800 + i] = zok ? src[gbase + zl * 800 + i] : 0xFFFFFFFFu;
        }
        __syncthreads();
        // P2: w-erode X[zl] -> WA
        for (int i = tid; i < 800; i += 256) {
            int j = i % W5;
            unsigned w = X[xs * 800 + i];
            unsigned l = j > 0 ? X[xs * 800 + i - 1] : 0xFFFFFFFFu;
            unsigned r = j < 4 ? X[xs * 800 + i + 1] : 0xFFFFFFFFu;
            WA[i] = w & ((w << 1) | (l >> 31)) & ((w >> 1) | (r << 31));
        }
        __syncthreads();
        // P3: h-erode WA -> WH[zl]
        {
            int ws = (zl + 6) % 3;
            for (int i = tid; i < 800; i += 256) {
                int r = i / W5;
                unsigned w = WA[i];
                unsigned up = r > 0   ? WA[i - W5] : 0xFFFFFFFFu;
                unsigned dn = r < 159 ? WA[i + W5] : 0xFFFFFFFFu;
                WH[ws * 800 + i] = w & up & dn;
            }
        }
        __syncthreads();
        // P4: z-erode -> E[zl-1] (OOB slice -> 0)
        int ze = zl - 1;
        int es = (ze + 2) & 1;
        {
            bool zev = ((unsigned)ze < 160u);
            int wa = (ze + 5) % 3, wb = (ze + 6) % 3, wc = (ze + 7) % 3;
            for (int i = tid; i < 800; i += 256) {
                unsigned e = WH[wa * 800 + i] & WH[wb * 800 + i] & WH[wc * 800 + i];
                E[es * 800 + i] = zev ? e : 0u;
            }
        }
        __syncthreads();
        // P5: w-dilate E[zl-1] -> WD
        for (int i = tid; i < 800; i += 256) {
            int j = i % W5;
            unsigned w = E[es * 800 + i];
            unsigned l = j > 0 ? E[es * 800 + i - 1] : 0u;
            unsigned r = j < 4 ? E[es * 800 + i + 1] : 0u;
            WD[i] = w | (w << 1) | (l >> 31) | (w >> 1) | (r << 31);
        }
        __syncthreads();
        // P6: h-dilate WD -> D[zl-1]
        {
            int ds = (ze + 6) % 3;
            for (int i = tid; i < 800; i += 256) {
                int r = i / W5;
                unsigned w = WD[i];
                unsigned up = r > 0   ? WD[i - W5] : 0u;
                unsigned dn = r < 159 ? WD[i + W5] : 0u;
                D[ds * 800 + i] = w | up | dn;
            }
        }
        __syncthreads();
        // P7: combine at z = zl-2 (X ring4 -> no trailing sync needed)
        int z = zl - 2;
        if (z >= z0) {
            int da = (z + 5) % 3, db = (z + 6) % 3, dc = (z + 7) % 3;
            int xz = (z + 4) & 3;
            int ez = (z + 2) & 1;
            for (int i = tid; i < 800; i += 256) {
                unsigned open = D[da * 800 + i] | D[db * 800 + i] | D[dc * 800 + i];
                unsigned x = X[xz * 800 + i];
                dst[gbase + z * 800 + i] = x & (~open | E[ez * 800 + i]);
            }
        }
    }
}

__global__ void __launch_bounds__(256) k_skel(int flip) {
    extern __shared__ float sm[];
    int bi = blockIdx.x;
    if (bi < 500) p_skel_block(sm, bi, flip);
    else          y_skel_block((unsigned int*)sm, bi - 500, flip);
}

// Final clDice sums: sum(p_skel), sum(p_skel*y), sum(y_skel), sum(y_skel*p_orig)
__global__ void __launch_bounds__(256) k_cl_reduce() {
    int q = blockIdx.x * 256 + threadIdx.x;
    float4 ps = ((const float4*)g_Xp)[q];       // p skeleton (8 iters -> back in g_Xp)
    float4 po = ((const float4*)g_Porig)[q];
    unsigned wS = g_Yb[q >> 3];                 // y skeleton bits (8 iters -> g_Yb)
    unsigned wO = g_Yb0[q >> 3];                // original y bits
    int sh = (q & 7) * 4;
    unsigned ns = (wS >> sh) & 0xFu;
    unsigned no = (wO >> sh) & 0xFu;
    float ys0 = (float)(ns & 1),        ys1 = (float)((ns >> 1) & 1);
    float ys2 = (float)((ns >> 2) & 1), ys3 = (float)((ns >> 3) & 1);
    float yo0 = (float)(no & 1),        yo1 = (float)((no >> 1) & 1);
    float yo2 = (float)((no >> 2) & 1), yo3 = (float)((no >> 3) & 1);
    float sp  = ps.x + ps.y + ps.z + ps.w;
    float spy = ps.x * yo0 + ps.y * yo1 + ps.z * yo2 + ps.w * yo3;
    float sy  = ys0 + ys1 + ys2 + ys3;
    float syp = ys0 * po.x + ys1 * po.y + ys2 * po.z + ys3 * po.w;
    float vals[4] = {sp, spy, sy, syp};
    blockAddTo<4>(vals, g_acc + 10);
}

__global__ void k_fin(float* out) {
    double ce = g_acc[0] / (double)NTOT;
    double dsum = 0.0;
#pragma unroll
    for (int c = 0; c < 3; c++) {
        double I = g_acc[1 + c], P = g_acc[4 + c], T = g_acc[7 + c];
        dsum += (2.0 * I + 1e-5) / (P + T + 1e-5);
    }
    double base = ce + (1.0 - dsum / 3.0);
    double tprec = g_acc[11] / (g_acc[10] + 1e-6);
    double tsens = g_acc[13] / (g_acc[12] + 1e-6);
    double cl = 2.0 * tprec * tsens / (tprec + tsens + 1e-6);
    out[0] = (float)(base + 0.5 * (1.0 - cl));
}

extern "C" void kernel_launch(void* const* d_in, const int* in_sizes, int n_in,
                              void* d_out, int out_size) {
    const float* logits = (const float*)d_in[0];
    const int* target = (const int*)d_in[1];

    cudaFuncSetAttribute((const void*)k_skel,
                         cudaFuncAttributeMaxDynamicSharedMemorySize, SM_BYTES);

    k_zero<<<1, 32>>>();
    k_init<<<NQ / 256, 256>>>(logits, target);
    for (int it = 0; it < 8; ++it)
        k_skel<<<540, 256, SM_BYTES>>>(it & 1);
    k_cl_reduce<<<NQ / 256, 256>>>();
    k_fin<<<1, 1>>>((float*)d_out);
}

// round 5
// speedup vs baseline: 2.7360x; 1.0375x over previous
#include <cuda_runtime.h>
#include <cuda_fp16.h>

#define SVOL  4096000        // 160^3
#define NTOT  8192000        // 2 * 160^3
#define NQ    2048000        // NTOT / 4

// ---- p skeleton smem layout (halves), tile 16h x 32w ----
#define OFF_STAGE 0          // [20][48]
#define OFF_ROWMN 960        // [20][40]
#define OFF_M2D   1760       // ring3 [18][40]  (stride 720)
#define OFF_ERO   3920       // ring2 [18][40]  (stride 720)
#define OFF_RMAX  5360       // [18][32]
#define OFF_E2D   5936       // ring3 [16][32]  (stride 512)
// total 7472 halves = 14944 B

// ---- y bit skeleton smem layout (words) ----
#define W5    5
#define WSL   800
#define WBAT  128000
#define YW    256000
#define YOFF_X   0           // [800] current slice
#define YOFF_WT  800         // [800] shared transient (w-erode / w-dilate)
#define YOFF_WH  1600        // ring3 [800]
#define YOFF_E   4000        // ring2 [800]
#define YOFF_D   5600        // ring3 [800]
// total 8000 words = 32000 B

#define SM_BYTES 32000

#define HPINF __ushort_as_half((unsigned short)0x7C00)
#define HNINF __ushort_as_half((unsigned short)0xFC00)

struct __align__(8) h4 { __half2 a, b; };

__device__ double g_acc[14];
__device__ __half g_Xp[NTOT];
__device__ __half g_Xp2[NTOT];
__device__ float g_Porig[NTOT];
__device__ unsigned int g_Yb0[YW];
__device__ unsigned int g_Yb[YW];
__device__ unsigned int g_Yb2[YW];

__device__ __forceinline__ h4 h4fill(__half v) {
    h4 o; o.a = __half2half2(v); o.b = o.a; return o;
}
__device__ __forceinline__ h4 h4min3(h4 x, h4 y, h4 z) {
    h4 o;
    o.a = __hmin2(x.a, __hmin2(y.a, z.a));
    o.b = __hmin2(x.b, __hmin2(y.b, z.b));
    return o;
}
__device__ __forceinline__ h4 h4max3(h4 x, h4 y, h4 z) {
    h4 o;
    o.a = __hmax2(x.a, __hmax2(y.a, z.a));
    o.b = __hmax2(x.b, __hmax2(y.b, z.b));
    return o;
}
// out[i] = min(e[i-1], e[i], e[i+1]) over (l, c0..c3, r)
__device__ __forceinline__ h4 shiftMin(__half l, h4 c, __half r) {
    __half2 sl  = __halves2half2(l, __low2half(c.a));                 // (l,  e0)
    __half2 sr  = __halves2half2(__high2half(c.a), __low2half(c.b));  // (e1, e2)
    __half2 sr2 = __halves2half2(__high2half(c.b), r);                // (e3, r)
    h4 o;
    o.a = __hmin2(__hmin2(sl, c.a), sr);
    o.b = __hmin2(__hmin2(sr, c.b), sr2);
    return o;
}
__device__ __forceinline__ h4 shiftMax(__half l, h4 c, __half r) {
    __half2 sl  = __halves2half2(l, __low2half(c.a));
    __half2 sr  = __halves2half2(__high2half(c.a), __low2half(c.b));
    __half2 sr2 = __halves2half2(__high2half(c.b), r);
    h4 o;
    o.a = __hmax2(__hmax2(sl, c.a), sr);
    o.b = __hmax2(__hmax2(sr, c.b), sr2);
    return o;
}

template <int NV>
__device__ __forceinline__ void blockAddTo(const float* vals, double* gout) {
    __shared__ float red[NV][8];
    int tid = threadIdx.x, lane = tid & 31, w = tid >> 5;
#pragma unroll
    for (int k = 0; k < NV; k++) {
        float v = vals[k];
#pragma unroll
        for (int o = 16; o; o >>= 1) v += __shfl_down_sync(0xffffffffu, v, o);
        if (lane == 0) red[k][w] = v;
    }
    __syncthreads();
    if (w == 0) {
#pragma unroll
        for (int k = 0; k < NV; k++) {
            float v = (lane < 8) ? red[k][lane] : 0.0f;
#pragma unroll
            for (int o = 4; o; o >>= 1) v += __shfl_down_sync(0xffffffffu, v, o);
            if (lane == 0) atomicAdd(&gout[k], (double)v);
        }
    }
}

__global__ void k_zero() {
    if (threadIdx.x < 14) g_acc[threadIdx.x] = 0.0;
}

// Fused: log-softmax, CE, dice accumulators, p_v init (fp16 + fp32 copy), y bit-pack.
__global__ void __launch_bounds__(256) k_init(const float* __restrict__ logits,
                                              const int* __restrict__ target) {
    __shared__ unsigned char nib[256];
    int tid = threadIdx.x;
    int q = blockIdx.x * 256 + tid;
    int e = q * 4;
    int b = (e >= SVOL) ? 1 : 0;
    int s = e - b * SVOL;
    const float* lp = logits + (size_t)b * 3 * SVOL + s;
    float4 L0 = *(const float4*)(lp);
    float4 L1 = *(const float4*)(lp + SVOL);
    float4 L2 = *(const float4*)(lp + 2 * SVOL);
    int4 ti = ((const int4*)target)[q];
    int tg[4] = {ti.x, ti.y, ti.z, ti.w};
    float a0[4] = {L0.x, L0.y, L0.z, L0.w};
    float a1[4] = {L1.x, L1.y, L1.z, L1.w};
    float a2[4] = {L2.x, L2.y, L2.z, L2.w};

    float ce = 0.f, i0 = 0.f, i1 = 0.f, i2 = 0.f;
    float s0 = 0.f, s1 = 0.f, s2 = 0.f, c0 = 0.f, c1 = 0.f, c2 = 0.f;
    float pv[4];
    unsigned nb = 0;
#pragma unroll
    for (int j = 0; j < 4; j++) {
        float x0 = a0[j], x1 = a1[j], x2 = a2[j];
        float m = fmaxf(x0, fmaxf(x1, x2));
        float e0 = __expf(x0 - m), e1 = __expf(x1 - m), e2 = __expf(x2 - m);
        float sum = e0 + e1 + e2;
        float inv = 1.0f / sum;
        float p0 = e0 * inv, p1 = e1 * inv, p2 = e2 * inv;
        float ls = __logf(sum);
        int t = tg[j];
        float lt = (t == 0) ? x0 : ((t == 1) ? x1 : x2);
        ce += (m + ls - lt);
        s0 += p0; s1 += p1; s2 += p2;
        if (t == 0)      { i0 += p0; c0 += 1.f; }
        else if (t == 1) { i1 += p1; c1 += 1.f; }
        else             { i2 += p2; c2 += 1.f; }
        pv[j] = fminf(fmaxf(1.0f - p0, 0.0f), 1.0f);
        if (t != 0) nb |= (1u << j);
    }
    h4 PV;
    PV.a = __floats2half2_rn(pv[0], pv[1]);
    PV.b = __floats2half2_rn(pv[2], pv[3]);
    ((h4*)g_Xp)[q] = PV;
    float4 PF = {pv[0], pv[1], pv[2], pv[3]};
    ((float4*)g_Porig)[q] = PF;
    nib[tid] = (unsigned char)nb;
    __syncthreads();
    if (tid < 32) {
        unsigned w = 0;
#pragma unroll
        for (int k = 0; k < 8; k++) w |= ((unsigned)nib[tid * 8 + k]) << (4 * k);
        int wi = blockIdx.x * 32 + tid;
        g_Yb0[wi] = w;
        g_Yb[wi] = w;
    }

    float vals[10] = {ce, i0, i1, i2, s0, s1, s2, c0, c1, c2};
    blockAddTo<10>(vals, g_acc);
}

// ---------------- merged skeleton iteration -----------------
// blocks [0,800): fp16 p skeleton (tile 16h x 32w, zchunk 20).
// blocks [800,840): bit y skeleton.

__device__ __forceinline__ void p_skel_block(__half* sm, int bi, int flip) {
    __half* stage = sm + OFF_STAGE;
    __half* rowmn = sm + OFF_ROWMN;
    __half* m2d   = sm + OFF_M2D;
    __half* ero   = sm + OFF_ERO;
    __half* rmax  = sm + OFF_RMAX;
    __half* e2d   = sm + OFF_E2D;

    const __half* src = flip ? g_Xp2 : g_Xp;
    __half*       dst = flip ? g_Xp  : g_Xp2;

    int tid = threadIdx.x;
    int r = bi;
    int b = r / 400; r %= 400;
    int zc = r / 50; int t = r % 50;
    int h0 = (t / 5) * 16, w0 = (t % 5) * 32;
    int z0 = zc * 20, z1 = z0 + 19;
    int base = b * SVOL;

    // one-time pad fill (cols 0..5 and 42..47 stay +inf forever)
    for (int i = tid; i < 240; i += 256) {
        int row = i / 12, c = i % 12;
        stage[row * 48 + ((c < 6) ? c : c + 36)] = HPINF;
    }

    for (int zl = z0 - 2; zl <= z1 + 2; ++zl) {
        bool zok = ((unsigned)zl < 160u);
        // ---- A: stage x slice zl (rows h0-2..h0+17) ----
        for (int i = tid; i < 160; i += 256) {
            int row = i >> 3, qw = i & 7;
            int h = h0 + row - 2;
            h4 v = h4fill(HPINF);
            if (zok && (unsigned)h < 160u)
                v = *(const h4*)(src + base + (zl * 160 + h) * 160 + w0 + qw * 4);
            *(h4*)&stage[row * 48 + 8 + qw * 4] = v;
        }
        for (int i = tid; i < 80; i += 256) {            // halo w in {-2,-1,32,33}
            int row = i >> 2, k = i & 3;
            int w = (k < 2) ? (k - 2) : (k + 30);
            int h = h0 + row - 2, ww = w0 + w;
            __half v = HPINF;
            if (zok && (unsigned)h < 160u && (unsigned)ww < 160u)
                v = src[base + (zl * 160 + h) * 160 + ww];
            stage[row * 48 + 8 + w] = v;
        }
        __syncthreads();
        // ---- B: row-min along w ----
        for (int i = tid; i < 200; i += 256) {
            int g = i % 10, row = i / 10;
            const __half* sp = &stage[row * 48 + 4 + g * 4];
            h4 o = shiftMin(sp[-1], *(const h4*)sp, sp[4]);
            *(h4*)&rowmn[row * 40 + g * 4] = o;
        }
        __syncthreads();
        // ---- C: col-min -> m2d[zl] (ring3); z-min -> ero[zl-1] (ring2) ----
        int sl2 = (zl + 6) % 3;
        int sl1 = (zl + 5) % 3;
        int sl0 = (zl + 4) % 3;
        int ze = zl - 1;
        int eW = (ze + 2) & 1;
        bool zev = ((unsigned)ze < 160u);
        for (int i = tid; i < 180; i += 256) {
            int g = i % 10, mrow = i / 10;
            int off = mrow * 40 + g * 4;
            h4 r0 = *(h4*)&rowmn[off];
            h4 r1 = *(h4*)&rowmn[off + 40];
            h4 r2 = *(h4*)&rowmn[off + 80];
            h4 v = h4min3(r0, r1, r2);
            *(h4*)&m2d[sl2 * 720 + off] = v;
            h4 e;
            if (zev) {
                h4 ma = *(h4*)&m2d[sl0 * 720 + off];
                h4 mb = *(h4*)&m2d[sl1 * 720 + off];
                e = h4min3(v, ma, mb);
            } else {
                e = h4fill(HNINF);
            }
            *(h4*)&ero[eW * 720 + off] = e;
        }
        __syncthreads();
        // ---- D: row-max of ero[zl-1] ----
        for (int i = tid; i < 144; i += 256) {
            int g = i & 7, row = i >> 3;
            const __half* ep = &ero[eW * 720 + row * 40 + 4 + g * 4];
            h4 o = shiftMax(ep[-1], *(const h4*)ep, ep[4]);
            *(h4*)&rmax[row * 32 + g * 4] = o;
        }
        __syncthreads();
        // ---- E+F fused: col-max -> e2d[zl-1]; output slice z = zl-2 ----
        if (tid < 128) {
            int g = tid & 7, h = tid >> 3;
            int off = h * 32 + g * 4;
            h4 r0 = *(h4*)&rmax[off];
            h4 r1 = *(h4*)&rmax[off + 32];
            h4 r2 = *(h4*)&rmax[off + 64];
            h4 v = h4max3(r0, r1, r2);
            *(h4*)&e2d[sl1 * 512 + off] = v;

            int z = zl - 2;
            if (z >= z0) {
                int ia = (z + 5) % 3, ib = (z + 6) % 3;
                h4 ea = *(h4*)&e2d[ia * 512 + off];
                h4 eb = *(h4*)&e2d[ib * 512 + off];
                h4 op = h4max3(ea, eb, v);
                h4 er = *(h4*)&ero[(z & 1) * 720 + (h + 1) * 40 + 4 + g * 4];
                h4 xv = *(const h4*)(src + base + (z * 160 + h0 + h) * 160 + w0 + g * 4);
                __half2 z2 = __float2half2_rn(0.0f);
                h4 o;
                o.a = __hmax2(__hsub2(xv.a, __hmax2(__hsub2(op.a, er.a), z2)), z2);
                o.b = __hmax2(__hsub2(xv.b, __hmax2(__hsub2(op.b, er.b), z2)), z2);
                *(h4*)(dst + base + (z * 160 + h0 + h) * 160 + w0 + g * 4) = o;
            }
        }
        // no trailing sync: every cross-step hazard has >=1 barrier in between
    }
}

// Bit-domain y skeleton, 8 output slices per block, minimal smem.
__device__ __forceinline__ void y_skel_block(unsigned int* su, int bi2, int flip) {
    unsigned int* X  = su + YOFF_X;
    unsigned int* WT = su + YOFF_WT;
    unsigned int* WH = su + YOFF_WH;   // ring3
    unsigned int* E  = su + YOFF_E;    // ring2
    unsigned int* D  = su + YOFF_D;    // ring3

    const unsigned int* src = flip ? g_Yb2 : g_Yb;
    unsigned int*       dst = flip ? g_Yb  : g_Yb2;

    int tid = threadIdx.x;
    int b = bi2 / 20, c = bi2 % 20;
    int z0 = c * 8, z1 = z0 + 7;
    int gbase = b * WBAT;

    for (int zl = z0 - 2; zl <= z1 + 2; ++zl) {
        // P1: load X slice zl (OOB = all ones)
        {
            bool zok = ((unsigned)zl < 160u);
            for (int i = tid; i < 800; i += 256)
                X[i] = zok ? src[gbase + zl * 800 + i] : 0xFFFFFFFFu;
        }
        __syncthreads();
        // P2: w-erode X -> WT
        for (int i = tid; i < 800; i += 256) {
            int j = i % W5;
            unsigned w = X[i];
            unsigned l = j > 0 ? X[i - 1] : 0xFFFFFFFFu;
            unsigned r = j < 4 ? X[i + 1] : 0xFFFFFFFFu;
            WT[i] = w & ((w << 1) | (l >> 31)) & ((w >> 1) | (r << 31));
        }
        __syncthreads();
        // P3: h-erode WT -> WH[zl]
        {
            int ws = (zl + 6) % 3;
            for (int i = tid; i < 800; i += 256) {
                int r = i / W5;
                unsigned w = WT[i];
                unsigned up = r > 0   ? WT[i - W5] : 0xFFFFFFFFu;
                unsigned dn = r < 159 ? WT[i + W5] : 0xFFFFFFFFu;
                WH[ws * 800 + i] = w & up & dn;
            }
        }
        __syncthreads();
        // P4: z-erode -> E[zl-1] (OOB slice -> 0)
        int ze = zl - 1;
        int es = (ze + 2) & 1;
        {
            bool zev = ((unsigned)ze < 160u);
            int wa = (ze + 5) % 3, wb = (ze + 6) % 3, wc = (ze + 7) % 3;
            for (int i = tid; i < 800; i += 256) {
                unsigned e = WH[wa * 800 + i] & WH[wb * 800 + i] & WH[wc * 800 + i];
                E[es * 800 + i] = zev ? e : 0u;
            }
        }
        __syncthreads();
        // P5: w-dilate E[zl-1] -> WT
        for (int i = tid; i < 800; i += 256) {
            int j = i % W5;
            unsigned w = E[es * 800 + i];
            unsigned l = j > 0 ? E[es * 800 + i - 1] : 0u;
            unsigned r = j < 4 ? E[es * 800 + i + 1] : 0u;
            WT[i] = w | (w << 1) | (l >> 31) | (w >> 1) | (r << 31);
        }
        __syncthreads();
        // P6: h-dilate WT -> D[zl-1]
        {
            int ds = (ze + 6) % 3;
            for (int i = tid; i < 800; i += 256) {
                int r = i / W5;
                unsigned w = WT[i];
                unsigned up = r > 0   ? WT[i - W5] : 0u;
                unsigned dn = r < 159 ? WT[i + W5] : 0u;
                D[ds * 800 + i] = w | up | dn;
            }
        }
        __syncthreads();
        // P7: combine at z = zl-2, x re-read from global
        int z = zl - 2;
        if (z >= z0) {
            int da = (z + 5) % 3, db = (z + 6) % 3, dc = (z + 7) % 3;
            int ez = (z + 2) & 1;
            for (int i = tid; i < 800; i += 256) {
                unsigned open = D[da * 800 + i] | D[db * 800 + i] | D[dc * 800 + i];
                unsigned x = src[gbase + z * 800 + i];
                dst[gbase + z * 800 + i] = x & (~open | E[ez * 800 + i]);
            }
        }
    }
}

__global__ void __launch_bounds__(256, 6) k_skel(int flip) {
    extern __shared__ __half smh[];
    int bi = blockIdx.x;
    if (bi < 800) p_skel_block(smh, bi, flip);
    else          y_skel_block((unsigned int*)smh, bi - 800, flip);
}

// Final clDice sums
__global__ void __launch_bounds__(256) k_cl_reduce() {
    int q = blockIdx.x * 256 + threadIdx.x;
    h4 psh = ((const h4*)g_Xp)[q];              // p skeleton (fp16)
    float2 p01 = __half22float2(psh.a);
    float2 p23 = __half22float2(psh.b);
    float4 po = ((const float4*)g_Porig)[q];
    unsigned wS = g_Yb[q >> 3];
    unsigned wO = g_Yb0[q >> 3];
    int sh = (q & 7) * 4;
    unsigned ns = (wS >> sh) & 0xFu;
    unsigned no = (wO >> sh) & 0xFu;
    float ys0 = (float)(ns & 1),        ys1 = (float)((ns >> 1) & 1);
    float ys2 = (float)((ns >> 2) & 1), ys3 = (float)((ns >> 3) & 1);
    float yo0 = (float)(no & 1),        yo1 = (float)((no >> 1) & 1);
    float yo2 = (float)((no >> 2) & 1), yo3 = (float)((no >> 3) & 1);
    float sp  = p01.x + p01.y + p23.x + p23.y;
    float spy = p01.x * yo0 + p01.y * yo1 + p23.x * yo2 + p23.y * yo3;
    float sy  = ys0 + ys1 + ys2 + ys3;
    float syp = ys0 * po.x + ys1 * po.y + ys2 * po.z + ys3 * po.w;
    float vals[4] = {sp, spy, sy, syp};
    blockAddTo<4>(vals, g_acc + 10);
}

__global__ void k_fin(float* out) {
    double ce = g_acc[0] / (double)NTOT;
    double dsum = 0.0;
#pragma unroll
    for (int c = 0; c < 3; c++) {
        double I = g_acc[1 + c], P = g_acc[4 + c], T = g_acc[7 + c];
        dsum += (2.0 * I + 1e-5) / (P + T + 1e-5);
    }
    double base = ce + (1.0 - dsum / 3.0);
    double tprec = g_acc[11] / (g_acc[10] + 1e-6);
    double tsens = g_acc[13] / (g_acc[12] + 1e-6);
    double cl = 2.0 * tprec * tsens / (tprec + tsens + 1e-6);
    out[0] = (float)(base + 0.5 * (1.0 - cl));
}

extern "C" void kernel_launch(void* const* d_in, const int* in_sizes, int n_in,
                              void* d_out, int out_size) {
    const float* logits = (const float*)d_in[0];
    const int* target = (const int*)d_in[1];

    cudaFuncSetAttribute((const void*)k_skel,
                         cudaFuncAttributeMaxDynamicSharedMemorySize, SM_BYTES);

    k_zero<<<1, 32>>>();
    k_init<<<NQ / 256, 256>>>(logits, target);
    for (int it = 0; it < 8; ++it)
        k_skel<<<840, 256, SM_BYTES>>>(it & 1);
    k_cl_reduce<<<NQ / 256, 256>>>();
    k_fin<<<1, 1>>>((float*)d_out);
}

// round 6
// speedup vs baseline: 3.4708x; 1.2686x over previous
#include <cuda_runtime.h>
#include <cuda_fp16.h>

#define SVOL  4096000        // 160^3
#define NTOT  8192000        // 2 * 160^3
#define NQ    2048000        // NTOT / 4

// ---- p skeleton smem layout (halves), tile 32h x 32w, 2 z-slices per iter ----
#define OFF_STAGE 0          // 2 x [36][48]   (stride 1728)
#define OFF_ROWMN 3456       // 2 x [36][40]   (stride 1440)
#define OFF_M2D   6336       // ring4 [34][40] (stride 1360)
#define OFF_ERO   11776      // ring3 [34][40] (stride 1360)
#define OFF_RMAX  15856      // 2 x [34][32]   (stride 1088)
#define OFF_E2D   18032      // ring4 [32][32] (stride 1024)
#define SM_HALVES 22128
#define SM_BYTES  (SM_HALVES * 2)   // 44256

// ---- y bit skeleton smem layout (words) ----
#define W5    5
#define WSL   800
#define WBAT  128000
#define YW    256000
#define YOFF_X   0           // [800]
#define YOFF_WT  800         // [800] transient
#define YOFF_WH  1600        // ring3 [800]
#define YOFF_E   4000        // ring2 [800]
#define YOFF_D   5600        // ring3 [800]

#define HPINF __ushort_as_half((unsigned short)0x7C00)
#define HNINF __ushort_as_half((unsigned short)0xFC00)

struct __align__(8) h4 { __half2 a, b; };

__device__ double g_acc[14];
__device__ __half g_Xp[NTOT];
__device__ __half g_Xp2[NTOT];
__device__ float g_Porig[NTOT];
__device__ unsigned int g_Yb0[YW];
__device__ unsigned int g_Yb[YW];
__device__ unsigned int g_Yb2[YW];

__device__ __forceinline__ h4 h4fill(__half v) {
    h4 o; o.a = __half2half2(v); o.b = o.a; return o;
}
__device__ __forceinline__ h4 h4min3(h4 x, h4 y, h4 z) {
    h4 o;
    o.a = __hmin2(x.a, __hmin2(y.a, z.a));
    o.b = __hmin2(x.b, __hmin2(y.b, z.b));
    return o;
}
__device__ __forceinline__ h4 h4max3(h4 x, h4 y, h4 z) {
    h4 o;
    o.a = __hmax2(x.a, __hmax2(y.a, z.a));
    o.b = __hmax2(x.b, __hmax2(y.b, z.b));
    return o;
}
__device__ __forceinline__ h4 shiftMin(__half l, h4 c, __half r) {
    __half2 sl  = __halves2half2(l, __low2half(c.a));
    __half2 sr  = __halves2half2(__high2half(c.a), __low2half(c.b));
    __half2 sr2 = __halves2half2(__high2half(c.b), r);
    h4 o;
    o.a = __hmin2(__hmin2(sl, c.a), sr);
    o.b = __hmin2(__hmin2(sr, c.b), sr2);
    return o;
}
__device__ __forceinline__ h4 shiftMax(__half l, h4 c, __half r) {
    __half2 sl  = __halves2half2(l, __low2half(c.a));
    __half2 sr  = __halves2half2(__high2half(c.a), __low2half(c.b));
    __half2 sr2 = __halves2half2(__high2half(c.b), r);
    h4 o;
    o.a = __hmax2(__hmax2(sl, c.a), sr);
    o.b = __hmax2(__hmax2(sr, c.b), sr2);
    return o;
}

template <int NV>
__device__ __forceinline__ void blockAddTo(const float* vals, double* gout) {
    __shared__ float red[NV][8];
    int tid = threadIdx.x, lane = tid & 31, w = tid >> 5;
#pragma unroll
    for (int k = 0; k < NV; k++) {
        float v = vals[k];
#pragma unroll
        for (int o = 16; o; o >>= 1) v += __shfl_down_sync(0xffffffffu, v, o);
        if (lane == 0) red[k][w] = v;
    }
    __syncthreads();
    if (w == 0) {
#pragma unroll
        for (int k = 0; k < NV; k++) {
            float v = (lane < 8) ? red[k][lane] : 0.0f;
#pragma unroll
            for (int o = 4; o; o >>= 1) v += __shfl_down_sync(0xffffffffu, v, o);
            if (lane == 0) atomicAdd(&gout[k], (double)v);
        }
    }
}

__global__ void k_zero() {
    if (threadIdx.x < 14) g_acc[threadIdx.x] = 0.0;
}

__global__ void __launch_bounds__(256) k_init(const float* __restrict__ logits,
                                              const int* __restrict__ target) {
    __shared__ unsigned char nib[256];
    int tid = threadIdx.x;
    int q = blockIdx.x * 256 + tid;
    int e = q * 4;
    int b = (e >= SVOL) ? 1 : 0;
    int s = e - b * SVOL;
    const float* lp = logits + (size_t)b * 3 * SVOL + s;
    float4 L0 = *(const float4*)(lp);
    float4 L1 = *(const float4*)(lp + SVOL);
    float4 L2 = *(const float4*)(lp + 2 * SVOL);
    int4 ti = ((const int4*)target)[q];
    int tg[4] = {ti.x, ti.y, ti.z, ti.w};
    float a0[4] = {L0.x, L0.y, L0.z, L0.w};
    float a1[4] = {L1.x, L1.y, L1.z, L1.w};
    float a2[4] = {L2.x, L2.y, L2.z, L2.w};

    float ce = 0.f, i0 = 0.f, i1 = 0.f, i2 = 0.f;
    float s0 = 0.f, s1 = 0.f, s2 = 0.f, c0 = 0.f, c1 = 0.f, c2 = 0.f;
    float pv[4];
    unsigned nb = 0;
#pragma unroll
    for (int j = 0; j < 4; j++) {
        float x0 = a0[j], x1 = a1[j], x2 = a2[j];
        float m = fmaxf(x0, fmaxf(x1, x2));
        float e0 = __expf(x0 - m), e1 = __expf(x1 - m), e2 = __expf(x2 - m);
        float sum = e0 + e1 + e2;
        float inv = 1.0f / sum;
        float p0 = e0 * inv, p1 = e1 * inv, p2 = e2 * inv;
        float ls = __logf(sum);
        int t = tg[j];
        float lt = (t == 0) ? x0 : ((t == 1) ? x1 : x2);
        ce += (m + ls - lt);
        s0 += p0; s1 += p1; s2 += p2;
        if (t == 0)      { i0 += p0; c0 += 1.f; }
        else if (t == 1) { i1 += p1; c1 += 1.f; }
        else             { i2 += p2; c2 += 1.f; }
        pv[j] = fminf(fmaxf(1.0f - p0, 0.0f), 1.0f);
        if (t != 0) nb |= (1u << j);
    }
    h4 PV;
    PV.a = __floats2half2_rn(pv[0], pv[1]);
    PV.b = __floats2half2_rn(pv[2], pv[3]);
    ((h4*)g_Xp)[q] = PV;
    float4 PF = {pv[0], pv[1], pv[2], pv[3]};
    ((float4*)g_Porig)[q] = PF;
    nib[tid] = (unsigned char)nb;
    __syncthreads();
    if (tid < 32) {
        unsigned w = 0;
#pragma unroll
        for (int k = 0; k < 8; k++) w |= ((unsigned)nib[tid * 8 + k]) << (4 * k);
        int wi = blockIdx.x * 32 + tid;
        g_Yb0[wi] = w;
        g_Yb[wi] = w;
    }

    float vals[10] = {ce, i0, i1, i2, s0, s1, s2, c0, c1, c2};
    blockAddTo<10>(vals, g_acc);
}

// ---------------- merged skeleton iteration -----------------
// blocks [0,500): fp16 p skeleton (tile 32x32, zchunk 16, 2 slices/iter).
// blocks [500,580): bit y skeleton (chunk 4).

__device__ __forceinline__ void p_skel_block(__half* sm, int bi, int flip) {
    __half* stage = sm + OFF_STAGE;
    __half* rowmn = sm + OFF_ROWMN;
    __half* m2d   = sm + OFF_M2D;
    __half* ero   = sm + OFF_ERO;
    __half* rmax  = sm + OFF_RMAX;
    __half* e2d   = sm + OFF_E2D;

    const __half* src = flip ? g_Xp2 : g_Xp;
    __half*       dst = flip ? g_Xp  : g_Xp2;

    int tid = threadIdx.x;
    int r = bi;
    int b = r / 250; r %= 250;
    int zc = r / 25; int t = r % 25;
    int h0 = (t / 5) * 32, w0 = (t % 5) * 32;
    int z0 = zc * 16;
    int base = b * SVOL;

    // one-time pad fill (both stage buffers, cols 0..5 and 42..47 stay +inf)
    for (int i = tid; i < 864; i += 256) {
        int s = i / 432, j = i % 432;
        int row = j / 12, c = j % 12;
        stage[s * 1728 + row * 48 + ((c < 6) ? c : c + 36)] = HPINF;
    }

    for (int zb = z0 - 2; zb <= z0 + 16; zb += 2) {
        // ---- A: stage x slices zb, zb+1 ----
        for (int i = tid; i < 576; i += 256) {
            int s = i / 288, j = i % 288;
            int row = j >> 3, qw = j & 7;
            int zl = zb + s;
            int h = h0 + row - 2;
            h4 v = h4fill(HPINF);
            if ((unsigned)zl < 160u && (unsigned)h < 160u)
                v = *(const h4*)(src + base + (zl * 160 + h) * 160 + w0 + qw * 4);
            *(h4*)&stage[s * 1728 + row * 48 + 8 + qw * 4] = v;
        }
        for (int i = tid; i < 288; i += 256) {            // halos w in {-2,-1,32,33}
            int s = i / 144, j = i % 144;
            int row = j >> 2, k = j & 3;
            int w = (k < 2) ? (k - 2) : (k + 30);
            int zl = zb + s;
            int h = h0 + row - 2, ww = w0 + w;
            __half v = HPINF;
            if ((unsigned)zl < 160u && (unsigned)h < 160u && (unsigned)ww < 160u)
                v = src[base + (zl * 160 + h) * 160 + ww];
            stage[s * 1728 + row * 48 + 8 + w] = v;
        }
        __syncthreads();
        // ---- B: row-min along w (both slices) ----
        for (int i = tid; i < 720; i += 256) {
            int s = i / 360, j = i % 360;
            int g = j % 10, row = j / 10;
            const __half* sp = &stage[s * 1728 + row * 48 + 4 + g * 4];
            h4 o = shiftMin(sp[-1], *(const h4*)sp, sp[4]);
            *(h4*)&rowmn[s * 1440 + row * 40 + g * 4] = o;
        }
        __syncthreads();
        // ---- C: col-min -> m2d[zb], m2d[zb+1]; z-min -> ero[zb-1], ero[zb] ----
        int mA = (zb + 6) & 3, mB = (zb + 7) & 3;       // slots zb-2, zb-1
        int m0 = (zb + 8) & 3, m1 = (zb + 9) & 3;       // slots zb,   zb+1
        int e0s = (zb + 8) % 3, e1s = (zb + 9) % 3;     // ero slots zb-1, zb
        bool zv0 = ((unsigned)(zb - 1) < 160u);
        bool zv1 = ((unsigned)zb < 160u);
        for (int i = tid; i < 340; i += 256) {
            int g = i % 10, mrow = i / 10;
            int off = mrow * 40 + g * 4;
            h4 v0, v1;
            {
                h4 r0 = *(h4*)&rowmn[off];
                h4 r1 = *(h4*)&rowmn[off + 40];
                h4 r2 = *(h4*)&rowmn[off + 80];
                v0 = h4min3(r0, r1, r2);
            }
            {
                h4 r0 = *(h4*)&rowmn[1440 + off];
                h4 r1 = *(h4*)&rowmn[1440 + off + 40];
                h4 r2 = *(h4*)&rowmn[1440 + off + 80];
                v1 = h4min3(r0, r1, r2);
            }
            *(h4*)&m2d[m0 * 1360 + off] = v0;
            *(h4*)&m2d[m1 * 1360 + off] = v1;
            h4 ma = *(h4*)&m2d[mA * 1360 + off];
            h4 mb = *(h4*)&m2d[mB * 1360 + off];
            h4 eA = zv0 ? h4min3(ma, mb, v0) : h4fill(HNINF);
            h4 eB = zv1 ? h4min3(mb, v0, v1) : h4fill(HNINF);
            *(h4*)&ero[e0s * 1360 + off] = eA;
            *(h4*)&ero[e1s * 1360 + off] = eB;
        }
        __syncthreads();
        // ---- D: row-max of ero[zb-1], ero[zb] ----
        for (int i = tid; i < 544; i += 256) {
            int s = i / 272, j = i % 272;
            int g = j & 7, row = j >> 3;
            int es = s ? e1s : e0s;
            const __half* ep = &ero[es * 1360 + row * 40 + 4 + g * 4];
            h4 o = shiftMax(ep[-1], *(const h4*)ep, ep[4]);
            *(h4*)&rmax[s * 1088 + row * 32 + g * 4] = o;
        }
        __syncthreads();
        // ---- E+F fused: col-max -> e2d[zb-1], e2d[zb]; outputs z = zb-2, zb-1 ----
        {
            int g = tid & 7, h = tid >> 3;     // exactly 256 items
            int off = h * 32 + g * 4;
            h4 v0, v1;
            {
                h4 r0 = *(h4*)&rmax[off];
                h4 r1 = *(h4*)&rmax[off + 32];
                h4 r2 = *(h4*)&rmax[off + 64];
                v0 = h4max3(r0, r1, r2);       // e2d[zb-1]
            }
            {
                h4 r0 = *(h4*)&rmax[1088 + off];
                h4 r1 = *(h4*)&rmax[1088 + off + 32];
                h4 r2 = *(h4*)&rmax[1088 + off + 64];
                v1 = h4max3(r0, r1, r2);       // e2d[zb]
            }
            *(h4*)&e2d[((zb + 7) & 3) * 1024 + off] = v0;
            *(h4*)&e2d[((zb + 8) & 3) * 1024 + off] = v1;

            int za = zb - 2;
            if (za >= z0) {
                __half2 z2 = __float2half2_rn(0.0f);
                h4 ea = *(h4*)&e2d[((zb + 5) & 3) * 1024 + off];   // e2d[zb-3]
                h4 eb = *(h4*)&e2d[((zb + 6) & 3) * 1024 + off];   // e2d[zb-2]
                // output za = zb-2
                {
                    h4 op = h4max3(ea, eb, v0);
                    h4 er = *(h4*)&ero[((zb + 7) % 3) * 1360 + (h + 1) * 40 + 4 + g * 4];
                    h4 xv = *(const h4*)(src + base + (za * 160 + h0 + h) * 160 + w0 + g * 4);
                    h4 o;
                    o.a = __hmax2(__hsub2(xv.a, __hmax2(__hsub2(op.a, er.a), z2)), z2);
                    o.b = __hmax2(__hsub2(xv.b, __hmax2(__hsub2(op.b, er.b), z2)), z2);
                    *(h4*)(dst + base + (za * 160 + h0 + h) * 160 + w0 + g * 4) = o;
                }
                // output zb-1
                {
                    int zB = zb - 1;
                    h4 op = h4max3(eb, v0, v1);
                    h4 er = *(h4*)&ero[e0s * 1360 + (h + 1) * 40 + 4 + g * 4];
                    h4 xv = *(const h4*)(src + base + (zB * 160 + h0 + h) * 160 + w0 + g * 4);
                    h4 o;
                    o.a = __hmax2(__hsub2(xv.a, __hmax2(__hsub2(op.a, er.a), z2)), z2);
                    o.b = __hmax2(__hsub2(xv.b, __hmax2(__hsub2(op.b, er.b), z2)), z2);
                    *(h4*)(dst + base + (zB * 160 + h0 + h) * 160 + w0 + g * 4) = o;
                }
            }
        }
        // no trailing sync: next A touches only stage (>=2 barriers from its readers)
    }
}

// Bit-domain y skeleton, 4 output slices per block.
__device__ __forceinline__ void y_skel_block(unsigned int* su, int bi2, int flip) {
    unsigned int* X  = su + YOFF_X;
    unsigned int* WT = su + YOFF_WT;
    unsigned int* WH = su + YOFF_WH;   // ring3
    unsigned int* E  = su + YOFF_E;    // ring2
    unsigned int* D  = su + YOFF_D;    // ring3

    const unsigned int* src = flip ? g_Yb2 : g_Yb;
    unsigned int*       dst = flip ? g_Yb  : g_Yb2;

    int tid = threadIdx.x;
    int b = bi2 / 40, c = bi2 % 40;
    int z0 = c * 4, z1 = z0 + 3;
    int gbase = b * WBAT;

    for (int zl = z0 - 2; zl <= z1 + 2; ++zl) {
        {
            bool zok = ((unsigned)zl < 160u);
            for (int i = tid; i < 800; i += 256)
                X[i] = zok ? src[gbase + zl * 800 + i] : 0xFFFFFFFFu;
        }
        __syncthreads();
        for (int i = tid; i < 800; i += 256) {
            int j = i % W5;
            unsigned w = X[i];
            unsigned l = j > 0 ? X[i - 1] : 0xFFFFFFFFu;
            unsigned r = j < 4 ? X[i + 1] : 0xFFFFFFFFu;
            WT[i] = w & ((w << 1) | (l >> 31)) & ((w >> 1) | (r << 31));
        }
        __syncthreads();
        {
            int ws = (zl + 6) % 3;
            for (int i = tid; i < 800; i += 256) {
                int r = i / W5;
                unsigned w = WT[i];
                unsigned up = r > 0   ? WT[i - W5] : 0xFFFFFFFFu;
                unsigned dn = r < 159 ? WT[i + W5] : 0xFFFFFFFFu;
                WH[ws * 800 + i] = w & up & dn;
            }
        }
        __syncthreads();
        int ze = zl - 1;
        int es = (ze + 2) & 1;
        {
            bool zev = ((unsigned)ze < 160u);
            int wa = (ze + 5) % 3, wb = (ze + 6) % 3, wc = (ze + 7) % 3;
            for (int i = tid; i < 800; i += 256) {
                unsigned e = WH[wa * 800 + i] & WH[wb * 800 + i] & WH[wc * 800 + i];
                E[es * 800 + i] = zev ? e : 0u;
            }
        }
        __syncthreads();
        for (int i = tid; i < 800; i += 256) {
            int j = i % W5;
            unsigned w = E[es * 800 + i];
            unsigned l = j > 0 ? E[es * 800 + i - 1] : 0u;
            unsigned r = j < 4 ? E[es * 800 + i + 1] : 0u;
            WT[i] = w | (w << 1) | (l >> 31) | (w >> 1) | (r << 31);
        }
        __syncthreads();
        {
            int ds = (ze + 6) % 3;
            for (int i = tid; i < 800; i += 256) {
                int r = i / W5;
                unsigned w = WT[i];
                unsigned up = r > 0   ? WT[i - W5] : 0u;
                unsigned dn = r < 159 ? WT[i + W5] : 0u;
                D[ds * 800 + i] = w | up | dn;
            }
        }
        __syncthreads();
        int z = zl - 2;
        if (z >= z0) {
            int da = (z + 5) % 3, db = (z + 6) % 3, dc = (z + 7) % 3;
            int ez = (z + 2) & 1;
            for (int i = tid; i < 800; i += 256) {
                unsigned open = D[da * 800 + i] | D[db * 800 + i] | D[dc * 800 + i];
                unsigned x = src[gbase + z * 800 + i];
                dst[gbase + z * 800 + i] = x & (~open | E[ez * 800 + i]);
            }
        }
    }
}

__global__ void __launch_bounds__(256, 4) k_skel(int flip) {
    extern __shared__ __half smh[];
    int bi = blockIdx.x;
    if (bi < 500) p_skel_block(smh, bi, flip);
    else          y_skel_block((unsigned int*)smh, bi - 500, flip);
}

__global__ void __launch_bounds__(256) k_cl_reduce() {
    int q = blockIdx.x * 256 + threadIdx.x;
    h4 psh = ((const h4*)g_Xp)[q];
    float2 p01 = __half22float2(psh.a);
    float2 p23 = __half22float2(psh.b);
    float4 po = ((const float4*)g_Porig)[q];
    unsigned wS = g_Yb[q >> 3];
    unsigned wO = g_Yb0[q >> 3];
    int sh = (q & 7) * 4;
    unsigned ns = (wS >> sh) & 0xFu;
    unsigned no = (wO >> sh) & 0xFu;
    float ys0 = (float)(ns & 1),        ys1 = (float)((ns >> 1) & 1);
    float ys2 = (float)((ns >> 2) & 1), ys3 = (float)((ns >> 3) & 1);
    float yo0 = (float)(no & 1),        yo1 = (float)((no >> 1) & 1);
    float yo2 = (float)((no >> 2) & 1), yo3 = (float)((no >> 3) & 1);
    float sp  = p01.x + p01.y + p23.x + p23.y;
    float spy = p01.x * yo0 + p01.y * yo1 + p23.x * yo2 + p23.y * yo3;
    float sy  = ys0 + ys1 + ys2 + ys3;
    float syp = ys0 * po.x + ys1 * po.y + ys2 * po.z + ys3 * po.w;
    float vals[4] = {sp, spy, sy, syp};
    blockAddTo<4>(vals, g_acc + 10);
}

__global__ void k_fin(float* out) {
    double ce = g_acc[0] / (double)NTOT;
    double dsum = 0.0;
#pragma unroll
    for (int c = 0; c < 3; c++) {
        double I = g_acc[1 + c], P = g_acc[4 + c], T = g_acc[7 + c];
        dsum += (2.0 * I + 1e-5) / (P + T + 1e-5);
    }
    double base = ce + (1.0 - dsum / 3.0);
    double tprec = g_acc[11] / (g_acc[10] + 1e-6);
    double tsens = g_acc[13] / (g_acc[12] + 1e-6);
    double cl = 2.0 * tprec * tsens / (tprec + tsens + 1e-6);
    out[0] = (float)(base + 0.5 * (1.0 - cl));
}

extern "C" void kernel_launch(void* const* d_in, const int* in_sizes, int n_in,
                              void* d_out, int out_size) {
    const float* logits = (const float*)d_in[0];
    const int* target = (const int*)d_in[1];

    cudaFuncSetAttribute((const void*)k_skel,
                         cudaFuncAttributeMaxDynamicSharedMemorySize, SM_BYTES);

    k_zero<<<1, 32>>>();
    k_init<<<NQ / 256, 256>>>(logits, target);
    for (int it = 0; it < 8; ++it)
        k_skel<<<580, 256, SM_BYTES>>>(it & 1);
    k_cl_reduce<<<NQ / 256, 256>>>();
    k_fin<<<1, 1>>>((float*)d_out);
}